// round 8
// baseline (speedup 1.0000x reference)
#include <cuda_runtime.h>
#include <cuda_bf16.h>
#include <math.h>
#include <stdint.h>

#define NB_  32
#define NH_  64
#define ND_  512
#define NROPE_ 64
#define NHALF_ 32
#define SMAX_ 4096
#define BS_  64
#define IH_  64
#define ID_  128
#define TOPK_ 512
#define SCALE_ 0.04419417382415922f

typedef unsigned long long ull;

// ---------------- scratch ----------------
__device__ float    g_qr[NB_*NH_*ND_];
__device__ unsigned g_qq[NB_*IH_*32];
__device__ float    g_qs[NB_*IH_];
__device__ float    g_iscore[NB_*SMAX_];
__device__ int      g_sel[NB_*TOPK_];
__device__ int      g_has0[NB_];
__device__ float    g_pO[NB_*4*2*16*512];
__device__ float2   g_pml[NB_*4*2*16];

// ---------------- f32x2 helpers ----------------
#define FMA2(d, a, b, c) asm("fma.rn.f32x2 %0, %1, %2, %3;" : "=l"(d) : "l"(a), "l"(b), "l"(c))
__device__ __forceinline__ ull dup2(float x){ ull r; asm("mov.b64 %0, {%1, %1};" : "=l"(r) : "f"(x)); return r; }
__device__ __forceinline__ float2 unpack2(ull v){ float2 r; asm("mov.b64 {%0, %1}, %2;" : "=f"(r.x), "=f"(r.y) : "l"(v)); return r; }

// ---------------- cp.async helpers ----------------
__device__ __forceinline__ void cpa16(void* dst_s, const void* src) {
    unsigned ds = (unsigned)__cvta_generic_to_shared(dst_s);
    asm volatile("cp.async.cg.shared.global [%0], [%1], 16;" :: "r"(ds), "l"(src));
}
#define CP_COMMIT() asm volatile("cp.async.commit_group;")
#define CP_WAIT0()  asm volatile("cp.async.wait_group 0;")

// ---------------- int8 warp MMA ----------------
__device__ __forceinline__ void imma16832(int& d0, int& d1, int& d2, int& d3,
                                          int a0, int a1, int a2, int a3,
                                          int b0, int b1) {
    asm volatile("mma.sync.aligned.m16n8k32.row.col.s32.s8.s8.s32 "
                 "{%0,%1,%2,%3}, {%4,%5,%6,%7}, {%8,%9}, {%0,%1,%2,%3};"
                 : "+r"(d0), "+r"(d1), "+r"(d2), "+r"(d3)
                 : "r"(a0), "r"(a1), "r"(a2), "r"(a3), "r"(b0), "r"(b1));
}

// ---------------- kernel 1: fused rope + q_idx quant ----------------
__device__ __forceinline__ int quant1(float x, float scale) {
    float r = rintf(x / scale);
    r = fminf(fmaxf(r, -128.f), 127.f);
    return (int)r;
}

__global__ void prep_kernel(const float* __restrict__ q,
                            const float* __restrict__ cosp,
                            const float* __restrict__ sinp,
                            const float* __restrict__ q_idx) {
    int t = threadIdx.x;
    if (blockIdx.x < 1024) {
        int bh = blockIdx.x * 2 + (t >> 7);
        int b  = bh >> 6;
        int d  = (t & 127) * 4;
        const float* src = q + (size_t)bh * ND_;
        float4 v = *(const float4*)(src + d);
        float4 o;
        if (d < ND_ - NROPE_) {
            o = v;
        } else {
            int i0 = (d - (ND_ - NROPE_)) >> 1;
            float c0 = cosp[b*NHALF_ + i0],   s0 = sinp[b*NHALF_ + i0];
            float c1 = cosp[b*NHALF_ + i0+1], s1 = sinp[b*NHALF_ + i0+1];
            o.x = v.x*c0 - v.y*s0;
            o.y = v.x*s0 + v.y*c0;
            o.z = v.z*c1 - v.w*s1;
            o.w = v.z*s1 + v.w*c1;
        }
        *(float4*)(g_qr + (size_t)bh*ND_ + d) = o;
    } else {
        int row  = (blockIdx.x - 1024) * 8 + (t >> 5);
        int lane = t & 31;
        float4 v = *(const float4*)(q_idx + (size_t)row*ID_ + lane*4);
        float m = fmaxf(fmaxf(fabsf(v.x), fabsf(v.y)), fmaxf(fabsf(v.z), fabsf(v.w)));
        #pragma unroll
        for (int o = 16; o; o >>= 1) m = fmaxf(m, __shfl_xor_sync(0xffffffffu, m, o));
        float scale = fmaxf(m, 1e-12f) * (1.f/127.f);
        if (scale < 1e-6f) scale = 1.f;
        int q0 = quant1(v.x, scale), q1 = quant1(v.y, scale);
        int q2 = quant1(v.z, scale), q3 = quant1(v.w, scale);
        unsigned w = (q0 & 0xFF) | ((q1 & 0xFF) << 8) | ((q2 & 0xFF) << 16) | ((q3 & 0xFF) << 24);
        g_qq[row*32 + lane] = w;
        if (lane == 0) g_qs[row] = scale;
    }
}

// ---------------- kernel 2: indexer via tensor-core IMMA ----------------
// CTA = (chunk of 256 keys, batch). 256 threads / 8 warps.
// Warp w owns keys [w*32, w*32+32): 4 n-tiles x 4 m-tiles x 4 k-steps of m16n8k32.
__global__ void __launch_bounds__(256)
indexer_kernel(const float* __restrict__ k_idx_cache,
               const int* __restrict__ btbl,
               const int* __restrict__ seq_lens) {
    __shared__ int   sqq[IH_][36];   // q words, stride 36 -> conflict-free frags
    __shared__ float qss[IH_];
    __shared__ int4  ktv[256][9];    // k words (36 ints = 9 int4 per key)
    __shared__ float skc[256];

    int b = blockIdx.y, chunk = blockIdx.x;
    int t = threadIdx.x;
    int lane = t & 31, w = t >> 5;

    // load q words + scales
    {
        const int* src = (const int*)(g_qq + b*IH_*32);
        for (int i = t; i < IH_*32; i += 256) sqq[i >> 5][i & 31] = src[i];
        if (t < IH_) qss[t] = g_qs[b*IH_ + t];
    }

    // quantize this thread's key (2-pass; second read is L1-hot)
    int seqlen = seq_lens[b];
    {
        int s = chunk*256 + t;
        int cs = min(s, seqlen-1);
        int pg = btbl[(b << 6) + (cs >> 6)];
        const float4* kr = (const float4*)(k_idx_cache + ((size_t)pg*BS_ + (cs & 63)) * ID_);

        float mx = 0.f;
        #pragma unroll
        for (int i = 0; i < 32; i++) {
            float4 v = kr[i];
            mx = fmaxf(mx, fmaxf(fmaxf(fabsf(v.x), fabsf(v.y)), fmaxf(fabsf(v.z), fabsf(v.w))));
        }
        float scale = fmaxf(mx, 1e-12f) * (1.f/127.f);
        if (scale < 1e-6f) scale = 1.f;

        #pragma unroll
        for (int j = 0; j < 8; j++) {
            int kwj[4];
            #pragma unroll
            for (int u = 0; u < 4; u++) {
                float4 v = kr[j*4 + u];
                int q0 = quant1(v.x, scale), q1 = quant1(v.y, scale);
                int q2 = quant1(v.z, scale), q3 = quant1(v.w, scale);
                kwj[u] = (q0 & 0xFF) | ((q1 & 0xFF) << 8) | ((q2 & 0xFF) << 16) | ((q3 & 0xFF) << 24);
            }
            ktv[t][j] = make_int4(kwj[0], kwj[1], kwj[2], kwj[3]);
        }
        skc[t] = scale;
    }
    __syncthreads();

    // MMA phase
    float negInf = __int_as_float(0xff800000);
    int wbase = w * 32;
    int g4 = lane >> 2, l4 = lane & 3;

    #pragma unroll 1
    for (int nt = 0; nt < 4; nt++) {
        int kb = wbase + nt*8 + g4;
        const int* ktp = (const int*)&ktv[kb][0];
        int bf[8];
        #pragma unroll
        for (int kk = 0; kk < 4; kk++) {
            bf[kk*2+0] = ktp[kk*8 + l4];
            bf[kk*2+1] = ktp[kk*8 + 4 + l4];
        }
        float fc0 = 0.f, fc1 = 0.f;
        #pragma unroll
        for (int mt = 0; mt < 4; mt++) {
            int r0 = mt*16 + g4;
            int d0 = 0, d1 = 0, d2 = 0, d3 = 0;
            #pragma unroll
            for (int kk = 0; kk < 4; kk++) {
                int w0 = kk*8 + l4;
                int a0 = sqq[r0][w0],     a1 = sqq[r0+8][w0];
                int a2 = sqq[r0][w0+4],   a3 = sqq[r0+8][w0+4];
                imma16832(d0, d1, d2, d3, a0, a1, a2, a3, bf[kk*2], bf[kk*2+1]);
            }
            float q0 = qss[r0], q1 = qss[r0+8];
            fc0 += (float)d0 * q0 + (float)d2 * q1;
            fc1 += (float)d1 * q0 + (float)d3 * q1;
        }
        #pragma unroll
        for (int o = 4; o < 32; o <<= 1) {
            fc0 += __shfl_xor_sync(0xffffffffu, fc0, o);
            fc1 += __shfl_xor_sync(0xffffffffu, fc1, o);
        }
        if (lane < 4) {
            int keyl = wbase + nt*8 + lane*2;
            int pos = chunk*256 + keyl;
            float* dst = g_iscore + b*SMAX_ + pos;
            dst[0] = (pos     < seqlen) ? fc0 * skc[keyl]   : negInf;
            dst[1] = (pos + 1 < seqlen) ? fc1 * skc[keyl+1] : negInf;
        }
    }
}

// ---------------- kernel 3: exact top-k, 1 full pass + candidate refine ----------------
__device__ __forceinline__ int exscan512(int v, int* sh, int* total) {
    int t = threadIdx.x, lane = t & 31, wid = t >> 5;
    __syncthreads();
    int incl = v;
    #pragma unroll
    for (int o = 1; o < 32; o <<= 1) {
        int n = __shfl_up_sync(0xffffffffu, incl, o);
        if (lane >= o) incl += n;
    }
    if (lane == 31) sh[wid] = incl;
    __syncthreads();
    if (wid == 0) {
        int x = (lane < 16) ? sh[lane] : 0;
        #pragma unroll
        for (int o = 1; o < 16; o <<= 1) {
            int n = __shfl_up_sync(0xffffffffu, x, o);
            if (lane >= o) x += n;
        }
        if (lane < 16) sh[lane] = x;
    }
    __syncthreads();
    int base = wid ? sh[wid-1] : 0;
    *total = sh[15];
    return base + incl - v;
}

__device__ __forceinline__ void select_bin(int* hist, int* sscan, int* sinfo, int Krem) {
    int t = threadIdx.x, lane = t & 31, wid = t >> 5;
    int c = (t < 256) ? hist[t] : 0;
    int incl = c;
    #pragma unroll
    for (int o = 1; o < 32; o <<= 1) {
        int n = __shfl_up_sync(0xffffffffu, incl, o);
        if (lane >= o) incl += n;
    }
    if (lane == 31 && wid < 8) sscan[wid] = incl;
    __syncthreads();
    if (wid == 0) {
        int x = (lane < 8) ? sscan[lane] : 0;
        #pragma unroll
        for (int o = 1; o < 8; o <<= 1) {
            int n = __shfl_up_sync(0xffffffffu, x, o);
            if (lane >= o) x += n;
        }
        if (lane < 8) sscan[lane] = x;
        if (lane == 7) sinfo[2] = x;
    }
    __syncthreads();
    if (t < 256) {
        int P = incl + (wid ? sscan[wid-1] : 0);
        int above = sinfo[2] - P;
        if (above < Krem && Krem <= above + c) {
            sinfo[0] = t;
            sinfo[1] = Krem - above;
        }
    }
    __syncthreads();
}

__global__ void topk_kernel() {
    int b = blockIdx.x;
    __shared__ unsigned skey[SMAX_];
    __shared__ unsigned cand[SMAX_];
    __shared__ int hist[256];
    __shared__ int sscan[17];
    __shared__ int sinfo[3];
    __shared__ int ccnt;
    int t = threadIdx.x;   // 512 threads

    for (int i = t; i < SMAX_; i += 512) {
        unsigned u = __float_as_uint(g_iscore[b*SMAX_ + i]);
        skey[i] = (u & 0x80000000u) ? ~u : (u | 0x80000000u);
    }
    if (t == 0) ccnt = 0;
    if (t < 256) hist[t] = 0;
    __syncthreads();

    for (int i = t; i < SMAX_; i += 512)
        atomicAdd((unsigned*)&hist[skey[i] >> 24], 1u);
    __syncthreads();
    select_bin(hist, sscan, sinfo, TOPK_);
    unsigned b1 = (unsigned)sinfo[0];
    unsigned prefix = b1 << 24;
    int Krem = sinfo[1];

    for (int i = t; i < SMAX_; i += 512) {
        unsigned u = skey[i];
        if ((u >> 24) == b1) cand[atomicAdd((unsigned*)&ccnt, 1u)] = u;
    }
    __syncthreads();
    int L = ccnt;
    unsigned mask = 0xFF000000u;

    for (int shift = 16; shift >= 0; shift -= 8) {
        if (t < 256) hist[t] = 0;
        __syncthreads();
        for (int i = t; i < L; i += 512) {
            unsigned u = cand[i];
            if ((u & mask) == prefix) atomicAdd((unsigned*)&hist[(u >> shift) & 255], 1u);
        }
        __syncthreads();
        select_bin(hist, sscan, sinfo, Krem);
        prefix |= ((unsigned)sinfo[0]) << shift;
        mask   |= 0xFFu << shift;
        Krem = sinfo[1];
    }
    unsigned T = prefix;
    int R = Krem;

    int base = t * 8;
    int eqc = 0;
    #pragma unroll
    for (int i = 0; i < 8; i++) eqc += (skey[base+i] == T);
    int tot;
    int eqoff = exscan512(eqc, sscan, &tot);

    int kc = 0;
    unsigned kmask = 0;
    int er = eqoff;
    #pragma unroll
    for (int i = 0; i < 8; i++) {
        unsigned u = skey[base+i];
        bool eq = (u == T);
        bool kp = (u > T) || (eq && er < R);
        er += eq;
        if (base + i == 0) g_has0[b] = kp ? 1 : 0;
        kmask |= (unsigned)kp << i;
        kc += kp;
    }
    int koff = exscan512(kc, sscan, &tot);
    int p = koff;
    #pragma unroll
    for (int i = 0; i < 8; i++) {
        if ((kmask >> i) & 1) g_sel[b*TOPK_ + p++] = base + i;
    }
}

// ---------------- kernel 4: split-KV attention (256 keys per CTA, R5 layout) ----------------
struct AttnSmem {
    float q[16][ND_];       // 32768
    float k[2][64][128];    // 65536 swizzled
    float sc[16][256];      // 16384
};                          // 114688 B

extern __shared__ char smem_raw[];

__device__ __forceinline__ void prefetch_tile(AttnSmem& S, int buf, int tile, int ch,
                                              int selbase,
                                              const float* __restrict__ kv,
                                              const int* __restrict__ btbl,
                                              int bq, int t) {
    int kbase = tile << 6;
    int g = t & 31;
    int dstg = g ^ ((t >> 5) & 7);
    #pragma unroll
    for (int i = 0; i < 8; i++) {
        int r = (t >> 5) + (i << 3);
        int sp = g_sel[selbase + kbase + r];
        int pg = btbl[bq + (sp >> 6)];
        const float* src = kv + ((size_t)pg*BS_ + (sp & 63)) * ND_ + (ch << 7) + (g << 2);
        cpa16(&S.k[buf][r][dstg << 2], src);
    }
    CP_COMMIT();
}

__global__ void __launch_bounds__(256, 2)
attn_kernel(const float* __restrict__ kv,
            const float* __restrict__ attn_sink,
            const int* __restrict__ btbl) {
    AttnSmem& S = *(AttnSmem*)smem_raw;
    int hg = blockIdx.x, b = blockIdx.y, split = blockIdx.z;
    int t = threadIdx.x;
    int hbase = hg * 16;
    int selbase = b*TOPK_ + split*256;
    int bq = b << 6;
    int slot = (b*4 + hg)*2 + split;

    {
        const float* qr = g_qr + ((size_t)b*NH_ + hbase) * ND_;
        for (int i = t*4; i < 16*ND_; i += 1024)
            *(float4*)&S.q[0][i] = *(const float4*)(qr + i);
        for (int i = t; i < 16*256; i += 256) (&S.sc[0][0])[i] = 0.f;
    }
    prefetch_tile(S, 0, 0, 0, selbase, kv, btbl, bq, t);
    __syncthreads();

    int w  = t >> 5;
    int kx = t & 31;
    int x7 = kx & 7;
    int hg4 = (w >> 1) << 2;
    int dgb = (w & 1) << 4;

    // ======== phase A: scores ========
    ull accA[4][2];
    int buf = 0;
    #pragma unroll 1
    for (int s = 0; s < 16; s++) {
        CP_WAIT0();
        __syncthreads();
        if (s < 15) prefetch_tile(S, buf^1, (s+1) >> 2, (s+1) & 3, selbase, kv, btbl, bq, t);
        else        prefetch_tile(S, buf^1, 0, 0, selbase, kv, btbl, bq, t);
        int tile = s >> 2, ch = s & 3;
        if (ch == 0) {
            #pragma unroll
            for (int h = 0; h < 4; h++) { accA[h][0] = 0ull; accA[h][1] = 0ull; }
        }
        const float* kb0 = &S.k[buf][kx][0];
        const float* kb1 = &S.k[buf][kx+32][0];
        #pragma unroll
        for (int gg = 0; gg < 16; gg++) {
            int g = dgb + gg;
            int off = (g ^ x7) << 2;
            ulonglong2 ka = *(const ulonglong2*)(kb0 + off);
            ulonglong2 kc = *(const ulonglong2*)(kb1 + off);
            int d = (ch << 7) + (g << 2);
            #pragma unroll
            for (int h = 0; h < 4; h++) {
                ulonglong2 qa = *(const ulonglong2*)&S.q[hg4+h][d];
                FMA2(accA[h][0], qa.x, ka.x, accA[h][0]);
                FMA2(accA[h][0], qa.y, ka.y, accA[h][0]);
                FMA2(accA[h][1], qa.x, kc.x, accA[h][1]);
                FMA2(accA[h][1], qa.y, kc.y, accA[h][1]);
            }
        }
        if (ch == 3) {
            int j0 = (tile << 6) + kx, j1 = j0 + 32;
            #pragma unroll
            for (int h = 0; h < 4; h++) {
                float2 u0 = unpack2(accA[h][0]);
                float2 u1 = unpack2(accA[h][1]);
                atomicAdd(&S.sc[hg4+h][j0], (u0.x + u0.y) * SCALE_);
                atomicAdd(&S.sc[hg4+h][j1], (u1.x + u1.y) * SCALE_);
            }
        }
        buf ^= 1;
    }
    __syncthreads();

    if (split == 0 && t < 16) {
        if (g_sel[selbase] == 0) S.sc[t][0] += attn_sink[hbase + t];
    }
    __syncthreads();

    // ======== softmax partials (warp per 2 heads) ========
    {
        int jt = t & 31;
        #pragma unroll
        for (int hh = 0; hh < 2; hh++) {
            int hloc = 2*w + hh;
            float m = -3.4e38f;
            #pragma unroll
            for (int j = jt; j < 256; j += 32) m = fmaxf(m, S.sc[hloc][j]);
            #pragma unroll
            for (int o = 16; o; o >>= 1) m = fmaxf(m, __shfl_xor_sync(0xffffffffu, m, o));
            float sum = 0.f;
            #pragma unroll
            for (int j = jt; j < 256; j += 32) {
                float e = __expf(S.sc[hloc][j] - m);
                S.sc[hloc][j] = e;
                sum += e;
            }
            #pragma unroll
            for (int o = 16; o; o >>= 1) sum += __shfl_xor_sync(0xffffffffu, sum, o);
            if (jt == 0) g_pml[slot*16 + hloc] = make_float2(m, sum);
        }
    }

    // ======== phase C: 4 heads/thread (R5 layout) ========
    int hq = (t >> 6) << 2;
    int pd = t & 63;
    int gC = pd >> 1;
    int o2 = (pd & 1) << 1;
    #pragma unroll 1
    for (int ch = 0; ch < 4; ch++) {
        ull a0 = 0ull, a1 = 0ull, a2 = 0ull, a3 = 0ull;
        #pragma unroll 1
        for (int tile = 0; tile < 4; tile++) {
            CP_WAIT0();
            __syncthreads();
            int s = ch*4 + tile;
            if (s < 15) {
                int ns = s + 1;
                prefetch_tile(S, buf^1, ns & 3, ns >> 2, selbase, kv, btbl, bq, t);
            }
            int kbase = tile << 6;
            const float* pw0 = &S.sc[hq+0][kbase];
            const float* pw1 = &S.sc[hq+1][kbase];
            const float* pw2 = &S.sc[hq+2][kbase];
            const float* pw3 = &S.sc[hq+3][kbase];
            const float* kbB = &S.k[buf][0][0];
            #pragma unroll 4
            for (int j = 0; j < 64; j += 4) {
                float4 w0 = *(const float4*)(pw0 + j);
                float4 w1 = *(const float4*)(pw1 + j);
                float4 w2 = *(const float4*)(pw2 + j);
                float4 w3 = *(const float4*)(pw3 + j);
                #pragma unroll
                for (int jj = 0; jj < 4; jj++) {
                    int row = j + jj;
                    ull kp = *(const ull*)(kbB + (row << 7) + ((gC ^ (row & 7)) << 2) + o2);
                    FMA2(a0, dup2((&w0.x)[jj]), kp, a0);
                    FMA2(a1, dup2((&w1.x)[jj]), kp, a1);
                    FMA2(a2, dup2((&w2.x)[jj]), kp, a2);
                    FMA2(a3, dup2((&w3.x)[jj]), kp, a3);
                }
            }
            buf ^= 1;
        }
        int dloc = (ch << 7) + (pd << 1);
        float* po = g_pO + ((size_t)slot*16)*ND_;
        float2 u;
        u = unpack2(a0); *(float2*)(po + (size_t)(hq+0)*ND_ + dloc) = u;
        u = unpack2(a1); *(float2*)(po + (size_t)(hq+1)*ND_ + dloc) = u;
        u = unpack2(a2); *(float2*)(po + (size_t)(hq+2)*ND_ + dloc) = u;
        u = unpack2(a3); *(float2*)(po + (size_t)(hq+3)*ND_ + dloc) = u;
    }
}

// ---------------- kernel 5: flash combine + optional key-0 term ----------------
__global__ void combine_kernel(const float* __restrict__ kv,
                               const float* __restrict__ attn_sink,
                               const int* __restrict__ btbl,
                               float* __restrict__ out) {
    __shared__ float k0s[512];
    __shared__ float s0sh[16];
    int hg = blockIdx.x, b = blockIdx.y;
    int t = threadIdx.x;
    int hbase = hg * 16;

    const float* k0 = kv + (size_t)btbl[b << 6] * (BS_ * ND_);
    {
        int i = t * 2;
        *(float2*)(k0s + i) = *(const float2*)(k0 + i);
    }
    __syncthreads();

    int h = t >> 4, ln = t & 15;
    {
        const float* qr = g_qr + ((size_t)b*NH_ + hbase + h)*ND_ + ln*32;
        const float* kk = k0s + ln*32;
        float acc = 0.f;
        #pragma unroll
        for (int i = 0; i < 32; i++) acc = fmaf(qr[i], kk[i], acc);
        #pragma unroll
        for (int o = 8; o; o >>= 1) acc += __shfl_xor_sync(0xffffffffu, acc, o);
        if (ln == 0) s0sh[h] = acc * SCALE_ + attn_sink[hbase + h];
    }
    __syncthreads();

    int dbase = ln * 32;
    int slot0 = (b*4 + hg)*2;
    float2 ml0 = g_pml[slot0*16 + h];
    float2 ml1 = g_pml[(slot0+1)*16 + h];
    int has0 = g_has0[b];
    float sc0 = s0sh[h];
    float M = fmaxf(ml0.x, ml1.x);
    if (!has0) M = fmaxf(M, sc0);
    float a0 = expf(ml0.x - M), a1 = expf(ml1.x - M);
    float a2 = has0 ? 0.f : expf(sc0 - M);
    float inv = 1.f / (ml0.y * a0 + ml1.y * a1 + a2);
    float c0 = a0 * inv, c1 = a1 * inv, c2 = a2 * inv;

    const float* p0 = g_pO + ((size_t)slot0*16 + h)*ND_ + dbase;
    const float* p1 = g_pO + ((size_t)(slot0+1)*16 + h)*ND_ + dbase;
    float* po = out + ((size_t)b*NH_ + hbase + h)*ND_ + dbase;
    #pragma unroll
    for (int i = 0; i < 8; i++) {
        float4 v0 = *(const float4*)(p0 + i*4);
        float4 v1 = *(const float4*)(p1 + i*4);
        float4 vk = *(const float4*)(k0s + dbase + i*4);
        float4 o;
        o.x = v0.x*c0 + v1.x*c1 + vk.x*c2;
        o.y = v0.y*c0 + v1.y*c1 + vk.y*c2;
        o.z = v0.z*c0 + v1.z*c1 + vk.z*c2;
        o.w = v0.w*c0 + v1.w*c1 + vk.w*c2;
        *(float4*)(po + i*4) = o;
    }
}

// ---------------- launch ----------------
extern "C" void kernel_launch(void* const* d_in, const int* in_sizes, int n_in,
                              void* d_out, int out_size) {
    const float* q      = (const float*)d_in[0];
    const float* cosp   = (const float*)d_in[1];
    const float* sinp   = (const float*)d_in[2];
    const float* kv     = (const float*)d_in[3];
    const float* q_idx  = (const float*)d_in[4];
    const float* k_idx  = (const float*)d_in[5];
    const float* sink   = (const float*)d_in[6];
    const int*   btbl   = (const int*)d_in[7];
    const int*   slens  = (const int*)d_in[8];
    float* out = (float*)d_out;

    prep_kernel<<<1280, 256>>>(q, cosp, sinp, q_idx);
    indexer_kernel<<<dim3(16, NB_), 256>>>(k_idx, btbl, slens);
    topk_kernel<<<NB_, 512>>>();

    int smem = (int)sizeof(AttnSmem);
    cudaFuncSetAttribute(attn_kernel, cudaFuncAttributeMaxDynamicSharedMemorySize, smem);
    attn_kernel<<<dim3(4, NB_, 2), 256, smem>>>(kv, sink, btbl);
    combine_kernel<<<dim3(4, NB_), 256>>>(kv, sink, btbl, out);
}

// round 9
// speedup vs baseline: 1.1012x; 1.1012x over previous
#include <cuda_runtime.h>
#include <cuda_bf16.h>
#include <math.h>
#include <stdint.h>

#define NB_  32
#define NH_  64
#define ND_  512
#define NROPE_ 64
#define NHALF_ 32
#define SMAX_ 4096
#define BS_  64
#define IH_  64
#define ID_  128
#define TOPK_ 512
#define SCALE_ 0.04419417382415922f

typedef unsigned long long ull;

// ---------------- scratch ----------------
__device__ float    g_qr[NB_*NH_*ND_];
__device__ unsigned g_qq[NB_*IH_*32];
__device__ float    g_qs[NB_*IH_];
__device__ float    g_iscore[NB_*SMAX_];
__device__ int      g_sel[NB_*TOPK_];
__device__ int      g_has0[NB_];
__device__ float    g_pO[NB_*4*2*16*512];
__device__ float2   g_pml[NB_*4*2*16];

// ---------------- f32x2 helpers ----------------
#define FMA2(d, a, b, c) asm("fma.rn.f32x2 %0, %1, %2, %3;" : "=l"(d) : "l"(a), "l"(b), "l"(c))
__device__ __forceinline__ ull dup2(float x){ ull r; asm("mov.b64 %0, {%1, %1};" : "=l"(r) : "f"(x)); return r; }
__device__ __forceinline__ float2 unpack2(ull v){ float2 r; asm("mov.b64 {%0, %1}, %2;" : "=f"(r.x), "=f"(r.y) : "l"(v)); return r; }

// ---------------- tf32 MMA ----------------
__device__ __forceinline__ void mma_tf32(float& c0, float& c1, float& c2, float& c3,
                                         unsigned a0, unsigned a1, unsigned a2, unsigned a3,
                                         unsigned b0, unsigned b1) {
    asm volatile("mma.sync.aligned.m16n8k8.row.col.f32.tf32.tf32.f32 "
        "{%0,%1,%2,%3}, {%4,%5,%6,%7}, {%8,%9}, {%0,%1,%2,%3};"
        : "+f"(c0), "+f"(c1), "+f"(c2), "+f"(c3)
        : "r"(a0), "r"(a1), "r"(a2), "r"(a3), "r"(b0), "r"(b1));
}

// ---------------- cp.async helpers ----------------
__device__ __forceinline__ void cpa16(void* dst_s, const void* src) {
    unsigned ds = (unsigned)__cvta_generic_to_shared(dst_s);
    asm volatile("cp.async.cg.shared.global [%0], [%1], 16;" :: "r"(ds), "l"(src));
}
#define CP_COMMIT() asm volatile("cp.async.commit_group;")
#define CP_WAIT0()  asm volatile("cp.async.wait_group 0;")

// ---------------- kernel 1: fused rope + q_idx quant ----------------
__device__ __forceinline__ int quant1(float x, float scale) {
    float r = rintf(x / scale);
    r = fminf(fmaxf(r, -128.f), 127.f);
    return (int)r;
}

__global__ void prep_kernel(const float* __restrict__ q,
                            const float* __restrict__ cosp,
                            const float* __restrict__ sinp,
                            const float* __restrict__ q_idx) {
    int t = threadIdx.x;
    if (blockIdx.x < 1024) {
        int bh = blockIdx.x * 2 + (t >> 7);
        int b  = bh >> 6;
        int d  = (t & 127) * 4;
        const float* src = q + (size_t)bh * ND_;
        float4 v = *(const float4*)(src + d);
        float4 o;
        if (d < ND_ - NROPE_) {
            o = v;
        } else {
            int i0 = (d - (ND_ - NROPE_)) >> 1;
            float c0 = cosp[b*NHALF_ + i0],   s0 = sinp[b*NHALF_ + i0];
            float c1 = cosp[b*NHALF_ + i0+1], s1 = sinp[b*NHALF_ + i0+1];
            o.x = v.x*c0 - v.y*s0;
            o.y = v.x*s0 + v.y*c0;
            o.z = v.z*c1 - v.w*s1;
            o.w = v.z*s1 + v.w*c1;
        }
        *(float4*)(g_qr + (size_t)bh*ND_ + d) = o;
    } else {
        int row  = (blockIdx.x - 1024) * 8 + (t >> 5);
        int lane = t & 31;
        float4 v = *(const float4*)(q_idx + (size_t)row*ID_ + lane*4);
        float m = fmaxf(fmaxf(fabsf(v.x), fabsf(v.y)), fmaxf(fabsf(v.z), fabsf(v.w)));
        #pragma unroll
        for (int o = 16; o; o >>= 1) m = fmaxf(m, __shfl_xor_sync(0xffffffffu, m, o));
        float scale = fmaxf(m, 1e-12f) * (1.f/127.f);
        if (scale < 1e-6f) scale = 1.f;
        int q0 = quant1(v.x, scale), q1 = quant1(v.y, scale);
        int q2 = quant1(v.z, scale), q3 = quant1(v.w, scale);
        unsigned w = (q0 & 0xFF) | ((q1 & 0xFF) << 8) | ((q2 & 0xFF) << 16) | ((q3 & 0xFF) << 24);
        g_qq[row*32 + lane] = w;
        if (lane == 0) g_qs[row] = scale;
    }
}

// ---------------- kernel 2: indexer, key-per-thread dp4a (measured best) ----------------
__global__ void __launch_bounds__(256)
indexer_kernel(const float* __restrict__ k_idx_cache,
               const int* __restrict__ btbl,
               const int* __restrict__ seq_lens) {
    __shared__ int4  sqq[IH_][8];
    __shared__ float sqs[IH_];
    int b = blockIdx.y, chunk = blockIdx.x;
    int t = threadIdx.x;

    const int4* src = (const int4*)(g_qq + b*IH_*32);
    for (int i = t; i < IH_*8; i += 256) ((int4*)sqq)[i] = src[i];
    if (t < IH_) sqs[t] = g_qs[b*IH_ + t];
    __syncthreads();

    int seqlen = seq_lens[b];
    int s = chunk*256 + t;
    int cs = min(s, seqlen-1);
    int pg = btbl[(b << 6) + (cs >> 6)];
    const float4* kr = (const float4*)(k_idx_cache + ((size_t)pg*BS_ + (cs & 63)) * ID_);

    float mx = 0.f;
    #pragma unroll
    for (int i = 0; i < 32; i++) {
        float4 v = kr[i];
        mx = fmaxf(mx, fmaxf(fmaxf(fabsf(v.x), fabsf(v.y)), fmaxf(fabsf(v.z), fabsf(v.w))));
    }
    float scale = fmaxf(mx, 1e-12f) * (1.f/127.f);
    if (scale < 1e-6f) scale = 1.f;

    int kw[32];
    #pragma unroll
    for (int i = 0; i < 32; i++) {
        float4 v = kr[i];
        int q0 = quant1(v.x, scale), q1 = quant1(v.y, scale);
        int q2 = quant1(v.z, scale), q3 = quant1(v.w, scale);
        kw[i] = (q0 & 0xFF) | ((q1 & 0xFF) << 8) | ((q2 & 0xFF) << 16) | ((q3 & 0xFF) << 24);
    }

    float tot = 0.f;
    #pragma unroll 4
    for (int h = 0; h < IH_; h += 2) {
        int a0 = 0, a1 = 0;
        #pragma unroll
        for (int wb = 0; wb < 8; wb++) {
            int4 x = sqq[h][wb];
            int4 y = sqq[h+1][wb];
            a0 = __dp4a(kw[wb*4+0], x.x, a0);
            a0 = __dp4a(kw[wb*4+1], x.y, a0);
            a0 = __dp4a(kw[wb*4+2], x.z, a0);
            a0 = __dp4a(kw[wb*4+3], x.w, a0);
            a1 = __dp4a(kw[wb*4+0], y.x, a1);
            a1 = __dp4a(kw[wb*4+1], y.y, a1);
            a1 = __dp4a(kw[wb*4+2], y.z, a1);
            a1 = __dp4a(kw[wb*4+3], y.w, a1);
        }
        tot = fmaf((float)a0, sqs[h],   tot);
        tot = fmaf((float)a1, sqs[h+1], tot);
    }
    g_iscore[b*SMAX_ + s] = (s < seqlen) ? tot * scale : __int_as_float(0xff800000);
}

// ---------------- kernel 3: exact top-k, 1 full pass + candidate refine ----------------
__device__ __forceinline__ int exscan512(int v, int* sh, int* total) {
    int t = threadIdx.x, lane = t & 31, wid = t >> 5;
    __syncthreads();
    int incl = v;
    #pragma unroll
    for (int o = 1; o < 32; o <<= 1) {
        int n = __shfl_up_sync(0xffffffffu, incl, o);
        if (lane >= o) incl += n;
    }
    if (lane == 31) sh[wid] = incl;
    __syncthreads();
    if (wid == 0) {
        int x = (lane < 16) ? sh[lane] : 0;
        #pragma unroll
        for (int o = 1; o < 16; o <<= 1) {
            int n = __shfl_up_sync(0xffffffffu, x, o);
            if (lane >= o) x += n;
        }
        if (lane < 16) sh[lane] = x;
    }
    __syncthreads();
    int base = wid ? sh[wid-1] : 0;
    *total = sh[15];
    return base + incl - v;
}

__device__ __forceinline__ void select_bin(int* hist, int* sscan, int* sinfo, int Krem) {
    int t = threadIdx.x, lane = t & 31, wid = t >> 5;
    int c = (t < 256) ? hist[t] : 0;
    int incl = c;
    #pragma unroll
    for (int o = 1; o < 32; o <<= 1) {
        int n = __shfl_up_sync(0xffffffffu, incl, o);
        if (lane >= o) incl += n;
    }
    if (lane == 31 && wid < 8) sscan[wid] = incl;
    __syncthreads();
    if (wid == 0) {
        int x = (lane < 8) ? sscan[lane] : 0;
        #pragma unroll
        for (int o = 1; o < 8; o <<= 1) {
            int n = __shfl_up_sync(0xffffffffu, x, o);
            if (lane >= o) x += n;
        }
        if (lane < 8) sscan[lane] = x;
        if (lane == 7) sinfo[2] = x;
    }
    __syncthreads();
    if (t < 256) {
        int P = incl + (wid ? sscan[wid-1] : 0);
        int above = sinfo[2] - P;
        if (above < Krem && Krem <= above + c) {
            sinfo[0] = t;
            sinfo[1] = Krem - above;
        }
    }
    __syncthreads();
}

__global__ void topk_kernel() {
    int b = blockIdx.x;
    __shared__ unsigned skey[SMAX_];
    __shared__ unsigned cand[SMAX_];
    __shared__ int hist[256];
    __shared__ int sscan[17];
    __shared__ int sinfo[3];
    __shared__ int ccnt;
    int t = threadIdx.x;

    for (int i = t; i < SMAX_; i += 512) {
        unsigned u = __float_as_uint(g_iscore[b*SMAX_ + i]);
        skey[i] = (u & 0x80000000u) ? ~u : (u | 0x80000000u);
    }
    if (t == 0) ccnt = 0;
    if (t < 256) hist[t] = 0;
    __syncthreads();

    for (int i = t; i < SMAX_; i += 512)
        atomicAdd((unsigned*)&hist[skey[i] >> 24], 1u);
    __syncthreads();
    select_bin(hist, sscan, sinfo, TOPK_);
    unsigned b1 = (unsigned)sinfo[0];
    unsigned prefix = b1 << 24;
    int Krem = sinfo[1];

    for (int i = t; i < SMAX_; i += 512) {
        unsigned u = skey[i];
        if ((u >> 24) == b1) cand[atomicAdd((unsigned*)&ccnt, 1u)] = u;
    }
    __syncthreads();
    int L = ccnt;
    unsigned mask = 0xFF000000u;

    for (int shift = 16; shift >= 0; shift -= 8) {
        if (t < 256) hist[t] = 0;
        __syncthreads();
        for (int i = t; i < L; i += 512) {
            unsigned u = cand[i];
            if ((u & mask) == prefix) atomicAdd((unsigned*)&hist[(u >> shift) & 255], 1u);
        }
        __syncthreads();
        select_bin(hist, sscan, sinfo, Krem);
        prefix |= ((unsigned)sinfo[0]) << shift;
        mask   |= 0xFFu << shift;
        Krem = sinfo[1];
    }
    unsigned T = prefix;
    int R = Krem;

    int base = t * 8;
    int eqc = 0;
    #pragma unroll
    for (int i = 0; i < 8; i++) eqc += (skey[base+i] == T);
    int tot;
    int eqoff = exscan512(eqc, sscan, &tot);

    int kc = 0;
    unsigned kmask = 0;
    int er = eqoff;
    #pragma unroll
    for (int i = 0; i < 8; i++) {
        unsigned u = skey[base+i];
        bool eq = (u == T);
        bool kp = (u > T) || (eq && er < R);
        er += eq;
        if (base + i == 0) g_has0[b] = kp ? 1 : 0;
        kmask |= (unsigned)kp << i;
        kc += kp;
    }
    int koff = exscan512(kc, sscan, &tot);
    int p = koff;
    #pragma unroll
    for (int i = 0; i < 8; i++) {
        if ((kmask >> i) & 1) g_sel[b*TOPK_ + p++] = base + i;
    }
}

// ---------------- kernel 4: split-KV attention; phase A = tf32 MMA ----------------
#define QSTR 516

struct AttnSmem {
    float q[16*QSTR];       // 33024, padded stride 516 (conflict-free MMA A frags)
    float k[2][64][128];    // 65536 swizzled
    float sc[16][256];      // 16384
};                          // 114944 B

extern __shared__ char smem_raw[];

__device__ __forceinline__ void prefetch_tile(AttnSmem& S, int buf, int tile, int ch,
                                              int selbase,
                                              const float* __restrict__ kv,
                                              const int* __restrict__ btbl,
                                              int bq, int t) {
    int kbase = tile << 6;
    int g = t & 31;
    int dstg = g ^ ((t >> 5) & 7);
    #pragma unroll
    for (int i = 0; i < 8; i++) {
        int r = (t >> 5) + (i << 3);
        int sp = g_sel[selbase + kbase + r];
        int pg = btbl[bq + (sp >> 6)];
        const float* src = kv + ((size_t)pg*BS_ + (sp & 63)) * ND_ + (ch << 7) + (g << 2);
        cpa16(&S.k[buf][r][dstg << 2], src);
    }
    CP_COMMIT();
}

__global__ void __launch_bounds__(256, 2)
attn_kernel(const float* __restrict__ kv,
            const float* __restrict__ attn_sink,
            const int* __restrict__ btbl) {
    AttnSmem& S = *(AttnSmem*)smem_raw;
    int hg = blockIdx.x, b = blockIdx.y, split = blockIdx.z;
    int t = threadIdx.x;
    int hbase = hg * 16;
    int selbase = b*TOPK_ + split*256;
    int bq = b << 6;
    int slot = (b*4 + hg)*2 + split;

    // load q into padded layout
    {
        const float* qr = g_qr + ((size_t)b*NH_ + hbase) * ND_;
        for (int i = t*4; i < 16*ND_; i += 1024) {
            int row = i >> 9, col = i & 511;
            *(float4*)&S.q[row*QSTR + col] = *(const float4*)(qr + i);
        }
    }
    prefetch_tile(S, 0, 0, 0, selbase, kv, btbl, bq, t);
    __syncthreads();

    int w    = t >> 5;
    int lane = t & 31;
    int g4 = lane >> 2, l4 = lane & 3;

    // ======== phase A: scores via tf32 MMA (3-term split) ========
    float c0 = 0.f, c1 = 0.f, c2 = 0.f, c3 = 0.f;
    int buf = 0;
    int rloc = (w << 3) + g4;       // this lane's key row within 64-key tile
    #pragma unroll 1
    for (int s = 0; s < 16; s++) {
        CP_WAIT0();
        __syncthreads();
        if (s < 15) prefetch_tile(S, buf^1, (s+1) >> 2, (s+1) & 3, selbase, kv, btbl, bq, t);
        else        prefetch_tile(S, buf^1, 0, 0, selbase, kv, btbl, bq, t);
        int tile = s >> 2, ch = s & 3;
        if (ch == 0) { c0 = 0.f; c1 = 0.f; c2 = 0.f; c3 = 0.f; }
        const float* kb  = &S.k[buf][rloc][0];
        const float* q0p = &S.q[g4*QSTR + (ch << 7) + l4];
        const float* q1p = &S.q[(g4+8)*QSTR + (ch << 7) + l4];
        #pragma unroll
        for (int ks = 0; ks < 16; ks++) {
            int k0 = ks << 3;
            float a0 = q0p[k0];
            float a1 = q1p[k0];
            float a2 = q0p[k0 + 4];
            float a3 = q1p[k0 + 4];
            int gb = k0 >> 2;
            float b0 = kb[((gb ^ g4) << 2) + l4];
            float b1 = kb[(((gb + 1) ^ g4) << 2) + l4];
            unsigned ah0 = __float_as_uint(a0) & 0xFFFFE000u;
            unsigned ah1 = __float_as_uint(a1) & 0xFFFFE000u;
            unsigned ah2 = __float_as_uint(a2) & 0xFFFFE000u;
            unsigned ah3 = __float_as_uint(a3) & 0xFFFFE000u;
            unsigned bh0 = __float_as_uint(b0) & 0xFFFFE000u;
            unsigned bh1 = __float_as_uint(b1) & 0xFFFFE000u;
            unsigned al0 = __float_as_uint(a0 - __uint_as_float(ah0));
            unsigned al1 = __float_as_uint(a1 - __uint_as_float(ah1));
            unsigned al2 = __float_as_uint(a2 - __uint_as_float(ah2));
            unsigned al3 = __float_as_uint(a3 - __uint_as_float(ah3));
            unsigned bl0 = __float_as_uint(b0 - __uint_as_float(bh0));
            unsigned bl1 = __float_as_uint(b1 - __uint_as_float(bh1));
            mma_tf32(c0,c1,c2,c3, ah0,ah1,ah2,ah3, bl0,bl1);
            mma_tf32(c0,c1,c2,c3, al0,al1,al2,al3, bh0,bh1);
            mma_tf32(c0,c1,c2,c3, ah0,ah1,ah2,ah3, bh0,bh1);
        }
        if (ch == 3) {
            // C frag: rows {g4, g4+8} (heads), cols {2*l4, 2*l4+1} within warp's 8-key n-tile
            int j0 = (tile << 6) + (w << 3) + (l4 << 1);
            S.sc[g4][j0]     = c0 * SCALE_;
            S.sc[g4][j0+1]   = c1 * SCALE_;
            S.sc[g4+8][j0]   = c2 * SCALE_;
            S.sc[g4+8][j0+1] = c3 * SCALE_;
        }
        buf ^= 1;
    }
    __syncthreads();

    if (split == 0 && t < 16) {
        if (g_sel[selbase] == 0) S.sc[t][0] += attn_sink[hbase + t];
    }
    __syncthreads();

    // ======== softmax partials (warp per 2 heads) ========
    {
        int jt = t & 31;
        #pragma unroll
        for (int hh = 0; hh < 2; hh++) {
            int hloc = 2*w + hh;
            float m = -3.4e38f;
            #pragma unroll
            for (int j = jt; j < 256; j += 32) m = fmaxf(m, S.sc[hloc][j]);
            #pragma unroll
            for (int o = 16; o; o >>= 1) m = fmaxf(m, __shfl_xor_sync(0xffffffffu, m, o));
            float sum = 0.f;
            #pragma unroll
            for (int j = jt; j < 256; j += 32) {
                float e = __expf(S.sc[hloc][j] - m);
                S.sc[hloc][j] = e;
                sum += e;
            }
            #pragma unroll
            for (int o = 16; o; o >>= 1) sum += __shfl_xor_sync(0xffffffffu, sum, o);
            if (jt == 0) g_pml[slot*16 + hloc] = make_float2(m, sum);
        }
    }

    // ======== phase C: 4 heads/thread scalar FMA2 (proven R5 layout) ========
    int hq = (t >> 6) << 2;
    int pd = t & 63;
    int gC = pd >> 1;
    int o2 = (pd & 1) << 1;
    #pragma unroll 1
    for (int ch = 0; ch < 4; ch++) {
        ull a0 = 0ull, a1 = 0ull, a2 = 0ull, a3 = 0ull;
        #pragma unroll 1
        for (int tile = 0; tile < 4; tile++) {
            CP_WAIT0();
            __syncthreads();
            int s = ch*4 + tile;
            if (s < 15) {
                int ns = s + 1;
                prefetch_tile(S, buf^1, ns & 3, ns >> 2, selbase, kv, btbl, bq, t);
            }
            int kbase = tile << 6;
            const float* pw0 = &S.sc[hq+0][kbase];
            const float* pw1 = &S.sc[hq+1][kbase];
            const float* pw2 = &S.sc[hq+2][kbase];
            const float* pw3 = &S.sc[hq+3][kbase];
            const float* kbB = &S.k[buf][0][0];
            #pragma unroll 4
            for (int j = 0; j < 64; j += 4) {
                float4 w0 = *(const float4*)(pw0 + j);
                float4 w1 = *(const float4*)(pw1 + j);
                float4 w2 = *(const float4*)(pw2 + j);
                float4 w3 = *(const float4*)(pw3 + j);
                #pragma unroll
                for (int jj = 0; jj < 4; jj++) {
                    int row = j + jj;
                    ull kp = *(const ull*)(kbB + (row << 7) + ((gC ^ (row & 7)) << 2) + o2);
                    FMA2(a0, dup2((&w0.x)[jj]), kp, a0);
                    FMA2(a1, dup2((&w1.x)[jj]), kp, a1);
                    FMA2(a2, dup2((&w2.x)[jj]), kp, a2);
                    FMA2(a3, dup2((&w3.x)[jj]), kp, a3);
                }
            }
            buf ^= 1;
        }
        int dloc = (ch << 7) + (pd << 1);
        float* po = g_pO + ((size_t)slot*16)*ND_;
        float2 u;
        u = unpack2(a0); *(float2*)(po + (size_t)(hq+0)*ND_ + dloc) = u;
        u = unpack2(a1); *(float2*)(po + (size_t)(hq+1)*ND_ + dloc) = u;
        u = unpack2(a2); *(float2*)(po + (size_t)(hq+2)*ND_ + dloc) = u;
        u = unpack2(a3); *(float2*)(po + (size_t)(hq+3)*ND_ + dloc) = u;
    }
}

// ---------------- kernel 5: flash combine + optional key-0 term ----------------
__global__ void combine_kernel(const float* __restrict__ kv,
                               const float* __restrict__ attn_sink,
                               const int* __restrict__ btbl,
                               float* __restrict__ out) {
    __shared__ float k0s[512];
    __shared__ float s0sh[16];
    int hg = blockIdx.x, b = blockIdx.y;
    int t = threadIdx.x;
    int hbase = hg * 16;

    const float* k0 = kv + (size_t)btbl[b << 6] * (BS_ * ND_);
    {
        int i = t * 2;
        *(float2*)(k0s + i) = *(const float2*)(k0 + i);
    }
    __syncthreads();

    int h = t >> 4, ln = t & 15;
    {
        const float* qr = g_qr + ((size_t)b*NH_ + hbase + h)*ND_ + ln*32;
        const float* kk = k0s + ln*32;
        float acc = 0.f;
        #pragma unroll
        for (int i = 0; i < 32; i++) acc = fmaf(qr[i], kk[i], acc);
        #pragma unroll
        for (int o = 8; o; o >>= 1) acc += __shfl_xor_sync(0xffffffffu, acc, o);
        if (ln == 0) s0sh[h] = acc * SCALE_ + attn_sink[hbase + h];
    }
    __syncthreads();

    int dbase = ln * 32;
    int slot0 = (b*4 + hg)*2;
    float2 ml0 = g_pml[slot0*16 + h];
    float2 ml1 = g_pml[(slot0+1)*16 + h];
    int has0 = g_has0[b];
    float sc0 = s0sh[h];
    float M = fmaxf(ml0.x, ml1.x);
    if (!has0) M = fmaxf(M, sc0);
    float a0 = expf(ml0.x - M), a1 = expf(ml1.x - M);
    float a2 = has0 ? 0.f : expf(sc0 - M);
    float inv = 1.f / (ml0.y * a0 + ml1.y * a1 + a2);
    float c0 = a0 * inv, c1 = a1 * inv, c2 = a2 * inv;

    const float* p0 = g_pO + ((size_t)slot0*16 + h)*ND_ + dbase;
    const float* p1 = g_pO + ((size_t)(slot0+1)*16 + h)*ND_ + dbase;
    float* po = out + ((size_t)b*NH_ + hbase + h)*ND_ + dbase;
    #pragma unroll
    for (int i = 0; i < 8; i++) {
        float4 v0 = *(const float4*)(p0 + i*4);
        float4 v1 = *(const float4*)(p1 + i*4);
        float4 vk = *(const float4*)(k0s + dbase + i*4);
        float4 o;
        o.x = v0.x*c0 + v1.x*c1 + vk.x*c2;
        o.y = v0.y*c0 + v1.y*c1 + vk.y*c2;
        o.z = v0.z*c0 + v1.z*c1 + vk.z*c2;
        o.w = v0.w*c0 + v1.w*c1 + vk.w*c2;
        *(float4*)(po + i*4) = o;
    }
}

// ---------------- launch ----------------
extern "C" void kernel_launch(void* const* d_in, const int* in_sizes, int n_in,
                              void* d_out, int out_size) {
    const float* q      = (const float*)d_in[0];
    const float* cosp   = (const float*)d_in[1];
    const float* sinp   = (const float*)d_in[2];
    const float* kv     = (const float*)d_in[3];
    const float* q_idx  = (const float*)d_in[4];
    const float* k_idx  = (const float*)d_in[5];
    const float* sink   = (const float*)d_in[6];
    const int*   btbl   = (const int*)d_in[7];
    const int*   slens  = (const int*)d_in[8];
    float* out = (float*)d_out;

    prep_kernel<<<1280, 256>>>(q, cosp, sinp, q_idx);
    indexer_kernel<<<dim3(16, NB_), 256>>>(k_idx, btbl, slens);
    topk_kernel<<<NB_, 512>>>();

    int smem = (int)sizeof(AttnSmem);
    cudaFuncSetAttribute(attn_kernel, cudaFuncAttributeMaxDynamicSharedMemorySize, smem);
    attn_kernel<<<dim3(4, NB_, 2), 256, smem>>>(kv, sink, btbl);
    combine_kernel<<<dim3(4, NB_), 256>>>(kv, sink, btbl, out);
}

// round 12
// speedup vs baseline: 1.1768x; 1.0686x over previous
#include <cuda_runtime.h>
#include <cuda_bf16.h>
#include <math.h>
#include <stdint.h>

#define NB_  32
#define NH_  64
#define ND_  512
#define NROPE_ 64
#define NHALF_ 32
#define SMAX_ 4096
#define BS_  64
#define IH_  64
#define ID_  128
#define TOPK_ 512
#define SCALE_ 0.04419417382415922f

typedef unsigned long long ull;

// ---------------- scratch ----------------
__device__ float    g_qr[NB_*NH_*ND_];
__device__ unsigned g_qq[NB_*IH_*32];
__device__ float    g_qs[NB_*IH_];
__device__ float    g_iscore[NB_*SMAX_];
__device__ int      g_sel[NB_*TOPK_];
__device__ int      g_has0[NB_];
__device__ float    g_pO[NB_*4*2*16*512];
__device__ float2   g_pml[NB_*4*2*16];

// ---------------- helpers ----------------
__device__ __forceinline__ float2 unpack2(ull v){ float2 r; asm("mov.b64 {%0, %1}, %2;" : "=f"(r.x), "=f"(r.y) : "l"(v)); return r; }

__device__ __forceinline__ void mma_tf32(float& c0, float& c1, float& c2, float& c3,
                                         unsigned a0, unsigned a1, unsigned a2, unsigned a3,
                                         unsigned b0, unsigned b1) {
    asm volatile("mma.sync.aligned.m16n8k8.row.col.f32.tf32.tf32.f32 "
        "{%0,%1,%2,%3}, {%4,%5,%6,%7}, {%8,%9}, {%0,%1,%2,%3};"
        : "+f"(c0), "+f"(c1), "+f"(c2), "+f"(c3)
        : "r"(a0), "r"(a1), "r"(a2), "r"(a3), "r"(b0), "r"(b1));
}

__device__ __forceinline__ void cpa16(void* dst_s, const void* src) {
    unsigned ds = (unsigned)__cvta_generic_to_shared(dst_s);
    asm volatile("cp.async.cg.shared.global [%0], [%1], 16;" :: "r"(ds), "l"(src));
}
#define CP_COMMIT() asm volatile("cp.async.commit_group;")
#define CP_WAIT0()  asm volatile("cp.async.wait_group 0;")

#define SPLIT_HL(x, hi, lo) do { \
    hi = __float_as_uint(x) & 0xFFFFE000u; \
    lo = __float_as_uint((x) - __uint_as_float(hi)); \
} while(0)

// ---------------- kernel 1: fused rope + q_idx quant ----------------
__device__ __forceinline__ int quant1(float x, float scale) {
    float r = rintf(x / scale);
    r = fminf(fmaxf(r, -128.f), 127.f);
    return (int)r;
}

__global__ void prep_kernel(const float* __restrict__ q,
                            const float* __restrict__ cosp,
                            const float* __restrict__ sinp,
                            const float* __restrict__ q_idx) {
    int t = threadIdx.x;
    if (blockIdx.x < 1024) {
        int bh = blockIdx.x * 2 + (t >> 7);
        int b  = bh >> 6;
        int d  = (t & 127) * 4;
        const float* src = q + (size_t)bh * ND_;
        float4 v = *(const float4*)(src + d);
        float4 o;
        if (d < ND_ - NROPE_) {
            o = v;
        } else {
            int i0 = (d - (ND_ - NROPE_)) >> 1;
            float c0 = cosp[b*NHALF_ + i0],   s0 = sinp[b*NHALF_ + i0];
            float c1 = cosp[b*NHALF_ + i0+1], s1 = sinp[b*NHALF_ + i0+1];
            o.x = v.x*c0 - v.y*s0;
            o.y = v.x*s0 + v.y*c0;
            o.z = v.z*c1 - v.w*s1;
            o.w = v.z*s1 + v.w*c1;
        }
        *(float4*)(g_qr + (size_t)bh*ND_ + d) = o;
    } else {
        int row  = (blockIdx.x - 1024) * 8 + (t >> 5);
        int lane = t & 31;
        float4 v = *(const float4*)(q_idx + (size_t)row*ID_ + lane*4);
        float m = fmaxf(fmaxf(fabsf(v.x), fabsf(v.y)), fmaxf(fabsf(v.z), fabsf(v.w)));
        #pragma unroll
        for (int o = 16; o; o >>= 1) m = fmaxf(m, __shfl_xor_sync(0xffffffffu, m, o));
        float scale = fmaxf(m, 1e-12f) * (1.f/127.f);
        if (scale < 1e-6f) scale = 1.f;
        int q0 = quant1(v.x, scale), q1 = quant1(v.y, scale);
        int q2 = quant1(v.z, scale), q3 = quant1(v.w, scale);
        unsigned w = (q0 & 0xFF) | ((q1 & 0xFF) << 8) | ((q2 & 0xFF) << 16) | ((q3 & 0xFF) << 24);
        g_qq[row*32 + lane] = w;
        if (lane == 0) g_qs[row] = scale;
    }
}

// ---------------- kernel 2: indexer, key-per-thread dp4a ----------------
__global__ void __launch_bounds__(256)
indexer_kernel(const float* __restrict__ k_idx_cache,
               const int* __restrict__ btbl,
               const int* __restrict__ seq_lens) {
    __shared__ int4  sqq[IH_][8];
    __shared__ float sqs[IH_];
    int b = blockIdx.y, chunk = blockIdx.x;
    int t = threadIdx.x;

    const int4* src = (const int4*)(g_qq + b*IH_*32);
    for (int i = t; i < IH_*8; i += 256) ((int4*)sqq)[i] = src[i];
    if (t < IH_) sqs[t] = g_qs[b*IH_ + t];
    __syncthreads();

    int seqlen = seq_lens[b];
    int s = chunk*256 + t;
    int cs = min(s, seqlen-1);
    int pg = btbl[(b << 6) + (cs >> 6)];
    const float4* kr = (const float4*)(k_idx_cache + ((size_t)pg*BS_ + (cs & 63)) * ID_);

    float mx = 0.f;
    #pragma unroll
    for (int i = 0; i < 32; i++) {
        float4 v = kr[i];
        mx = fmaxf(mx, fmaxf(fmaxf(fabsf(v.x), fabsf(v.y)), fmaxf(fabsf(v.z), fabsf(v.w))));
    }
    float scale = fmaxf(mx, 1e-12f) * (1.f/127.f);
    if (scale < 1e-6f) scale = 1.f;

    int kw[32];
    #pragma unroll
    for (int i = 0; i < 32; i++) {
        float4 v = kr[i];
        int q0 = quant1(v.x, scale), q1 = quant1(v.y, scale);
        int q2 = quant1(v.z, scale), q3 = quant1(v.w, scale);
        kw[i] = (q0 & 0xFF) | ((q1 & 0xFF) << 8) | ((q2 & 0xFF) << 16) | ((q3 & 0xFF) << 24);
    }

    float tot = 0.f;
    #pragma unroll 4
    for (int h = 0; h < IH_; h += 2) {
        int a0 = 0, a1 = 0;
        #pragma unroll
        for (int wb = 0; wb < 8; wb++) {
            int4 x = sqq[h][wb];
            int4 y = sqq[h+1][wb];
            a0 = __dp4a(kw[wb*4+0], x.x, a0);
            a0 = __dp4a(kw[wb*4+1], x.y, a0);
            a0 = __dp4a(kw[wb*4+2], x.z, a0);
            a0 = __dp4a(kw[wb*4+3], x.w, a0);
            a1 = __dp4a(kw[wb*4+0], y.x, a1);
            a1 = __dp4a(kw[wb*4+1], y.y, a1);
            a1 = __dp4a(kw[wb*4+2], y.z, a1);
            a1 = __dp4a(kw[wb*4+3], y.w, a1);
        }
        tot = fmaf((float)a0, sqs[h],   tot);
        tot = fmaf((float)a1, sqs[h+1], tot);
    }
    g_iscore[b*SMAX_ + s] = (s < seqlen) ? tot * scale : __int_as_float(0xff800000);
}

// ---------------- kernel 3: exact top-k ----------------
__device__ __forceinline__ int exscan512(int v, int* sh, int* total) {
    int t = threadIdx.x, lane = t & 31, wid = t >> 5;
    __syncthreads();
    int incl = v;
    #pragma unroll
    for (int o = 1; o < 32; o <<= 1) {
        int n = __shfl_up_sync(0xffffffffu, incl, o);
        if (lane >= o) incl += n;
    }
    if (lane == 31) sh[wid] = incl;
    __syncthreads();
    if (wid == 0) {
        int x = (lane < 16) ? sh[lane] : 0;
        #pragma unroll
        for (int o = 1; o < 16; o <<= 1) {
            int n = __shfl_up_sync(0xffffffffu, x, o);
            if (lane >= o) x += n;
        }
        if (lane < 16) sh[lane] = x;
    }
    __syncthreads();
    int base = wid ? sh[wid-1] : 0;
    *total = sh[15];
    return base + incl - v;
}

__device__ __forceinline__ void select_bin(int* hist, int* sscan, int* sinfo, int Krem) {
    int t = threadIdx.x, lane = t & 31, wid = t >> 5;
    int c = (t < 256) ? hist[t] : 0;
    int incl = c;
    #pragma unroll
    for (int o = 1; o < 32; o <<= 1) {
        int n = __shfl_up_sync(0xffffffffu, incl, o);
        if (lane >= o) incl += n;
    }
    if (lane == 31 && wid < 8) sscan[wid] = incl;
    __syncthreads();
    if (wid == 0) {
        int x = (lane < 8) ? sscan[lane] : 0;
        #pragma unroll
        for (int o = 1; o < 8; o <<= 1) {
            int n = __shfl_up_sync(0xffffffffu, x, o);
            if (lane >= o) x += n;
        }
        if (lane < 8) sscan[lane] = x;
        if (lane == 7) sinfo[2] = x;
    }
    __syncthreads();
    if (t < 256) {
        int P = incl + (wid ? sscan[wid-1] : 0);
        int above = sinfo[2] - P;
        if (above < Krem && Krem <= above + c) {
            sinfo[0] = t;
            sinfo[1] = Krem - above;
        }
    }
    __syncthreads();
}

__global__ void topk_kernel() {
    int b = blockIdx.x;
    __shared__ unsigned skey[SMAX_];
    __shared__ unsigned cand[SMAX_];
    __shared__ int hist[256];
    __shared__ int sscan[17];
    __shared__ int sinfo[3];
    __shared__ int ccnt;
    int t = threadIdx.x;

    for (int i = t; i < SMAX_; i += 512) {
        unsigned u = __float_as_uint(g_iscore[b*SMAX_ + i]);
        skey[i] = (u & 0x80000000u) ? ~u : (u | 0x80000000u);
    }
    if (t == 0) ccnt = 0;
    if (t < 256) hist[t] = 0;
    __syncthreads();

    for (int i = t; i < SMAX_; i += 512)
        atomicAdd((unsigned*)&hist[skey[i] >> 24], 1u);
    __syncthreads();
    select_bin(hist, sscan, sinfo, TOPK_);
    unsigned b1 = (unsigned)sinfo[0];
    unsigned prefix = b1 << 24;
    int Krem = sinfo[1];

    for (int i = t; i < SMAX_; i += 512) {
        unsigned u = skey[i];
        if ((u >> 24) == b1) cand[atomicAdd((unsigned*)&ccnt, 1u)] = u;
    }
    __syncthreads();
    int L = ccnt;
    unsigned mask = 0xFF000000u;

    for (int shift = 16; shift >= 0; shift -= 8) {
        if (t < 256) hist[t] = 0;
        __syncthreads();
        for (int i = t; i < L; i += 512) {
            unsigned u = cand[i];
            if ((u & mask) == prefix) atomicAdd((unsigned*)&hist[(u >> shift) & 255], 1u);
        }
        __syncthreads();
        select_bin(hist, sscan, sinfo, Krem);
        prefix |= ((unsigned)sinfo[0]) << shift;
        mask   |= 0xFFu << shift;
        Krem = sinfo[1];
    }
    unsigned T = prefix;
    int R = Krem;

    int base = t * 8;
    int eqc = 0;
    #pragma unroll
    for (int i = 0; i < 8; i++) eqc += (skey[base+i] == T);
    int tot;
    int eqoff = exscan512(eqc, sscan, &tot);

    int kc = 0;
    unsigned kmask = 0;
    int er = eqoff;
    #pragma unroll
    for (int i = 0; i < 8; i++) {
        unsigned u = skey[base+i];
        bool eq = (u == T);
        bool kp = (u > T) || (eq && er < R);
        er += eq;
        if (base + i == 0) g_has0[b] = kp ? 1 : 0;
        kmask |= (unsigned)kp << i;
        kc += kp;
    }
    int koff = exscan512(kc, sscan, &tot);
    int p = koff;
    #pragma unroll
    for (int i = 0; i < 8; i++) {
        if ((kmask >> i) & 1) g_sel[b*TOPK_ + p++] = base + i;
    }
}

// ---------------- kernel 4: split-KV attention; A and C on tf32 MMA ----------------
#define QSTR 516
#define SCSTR 260

struct AttnSmem {
    float q[16*QSTR];        // 33024
    float k[2][64][128];     // 65536 swizzled
    float sc[16][SCSTR];     // 16640 (stride 260 -> conflict-free A frags)
};                           // 115200 B

extern __shared__ char smem_raw[];

__device__ __forceinline__ void prefetch_tile(AttnSmem& S, int buf, int tile, int ch,
                                              int selbase,
                                              const float* __restrict__ kv,
                                              const int* __restrict__ btbl,
                                              int bq, int t) {
    int kbase = tile << 6;
    int g = t & 31;
    int dstg = g ^ ((t >> 5) & 7);
    #pragma unroll
    for (int i = 0; i < 8; i++) {
        int r = (t >> 5) + (i << 3);
        int sp = g_sel[selbase + kbase + r];
        int pg = btbl[bq + (sp >> 6)];
        const float* src = kv + ((size_t)pg*BS_ + (sp & 63)) * ND_ + (ch << 7) + (g << 2);
        cpa16(&S.k[buf][r][dstg << 2], src);
    }
    CP_COMMIT();
}

__global__ void __launch_bounds__(256, 2)
attn_kernel(const float* __restrict__ kv,
            const float* __restrict__ attn_sink,
            const int* __restrict__ btbl) {
    AttnSmem& S = *(AttnSmem*)smem_raw;
    int hg = blockIdx.x, b = blockIdx.y, split = blockIdx.z;
    int t = threadIdx.x;
    int hbase = hg * 16;
    int selbase = b*TOPK_ + split*256;
    int bq = b << 6;
    int slot = (b*4 + hg)*2 + split;

    {
        const float* qr = g_qr + ((size_t)b*NH_ + hbase) * ND_;
        for (int i = t*4; i < 16*ND_; i += 1024) {
            int row = i >> 9, col = i & 511;
            *(float4*)&S.q[row*QSTR + col] = *(const float4*)(qr + i);
        }
    }
    prefetch_tile(S, 0, 0, 0, selbase, kv, btbl, bq, t);
    __syncthreads();

    int w    = t >> 5;
    int lane = t & 31;
    int g4 = lane >> 2, l4 = lane & 3;

    // ======== phase A: scores via tf32 MMA (3-term split) ========
    float c0 = 0.f, c1 = 0.f, c2 = 0.f, c3 = 0.f;
    int buf = 0;
    int rloc = (w << 3) + g4;
    #pragma unroll 1
    for (int s = 0; s < 16; s++) {
        CP_WAIT0();
        __syncthreads();
        if (s < 15) prefetch_tile(S, buf^1, (s+1) >> 2, (s+1) & 3, selbase, kv, btbl, bq, t);
        else        prefetch_tile(S, buf^1, 0, 0, selbase, kv, btbl, bq, t);
        int tile = s >> 2, ch = s & 3;
        if (ch == 0) { c0 = 0.f; c1 = 0.f; c2 = 0.f; c3 = 0.f; }
        const float* kb  = &S.k[buf][rloc][0];
        const float* q0p = &S.q[g4*QSTR + (ch << 7) + l4];
        const float* q1p = &S.q[(g4+8)*QSTR + (ch << 7) + l4];
        #pragma unroll
        for (int ks = 0; ks < 16; ks++) {
            int k0 = ks << 3;
            float a0 = q0p[k0];
            float a1 = q1p[k0];
            float a2 = q0p[k0 + 4];
            float a3 = q1p[k0 + 4];
            int gb = k0 >> 2;
            float b0 = kb[((gb ^ g4) << 2) + l4];
            float b1 = kb[(((gb + 1) ^ g4) << 2) + l4];
            unsigned ah0, ah1, ah2, ah3, al0, al1, al2, al3, bh0, bh1, bl0, bl1;
            SPLIT_HL(a0, ah0, al0); SPLIT_HL(a1, ah1, al1);
            SPLIT_HL(a2, ah2, al2); SPLIT_HL(a3, ah3, al3);
            SPLIT_HL(b0, bh0, bl0); SPLIT_HL(b1, bh1, bl1);
            mma_tf32(c0,c1,c2,c3, ah0,ah1,ah2,ah3, bl0,bl1);
            mma_tf32(c0,c1,c2,c3, al0,al1,al2,al3, bh0,bh1);
            mma_tf32(c0,c1,c2,c3, ah0,ah1,ah2,ah3, bh0,bh1);
        }
        if (ch == 3) {
            int j0 = (tile << 6) + (w << 3) + (l4 << 1);
            S.sc[g4][j0]     = c0 * SCALE_;
            S.sc[g4][j0+1]   = c1 * SCALE_;
            S.sc[g4+8][j0]   = c2 * SCALE_;
            S.sc[g4+8][j0+1] = c3 * SCALE_;
        }
        buf ^= 1;
    }
    __syncthreads();

    if (split == 0 && t < 16) {
        if (g_sel[selbase] == 0) S.sc[t][0] += attn_sink[hbase + t];
    }
    __syncthreads();

    // ======== softmax partials (warp per 2 heads) ========
    {
        int jt = t & 31;
        #pragma unroll
        for (int hh = 0; hh < 2; hh++) {
            int hloc = 2*w + hh;
            float m = -3.4e38f;
            #pragma unroll
            for (int j = jt; j < 256; j += 32) m = fmaxf(m, S.sc[hloc][j]);
            #pragma unroll
            for (int o = 16; o; o >>= 1) m = fmaxf(m, __shfl_xor_sync(0xffffffffu, m, o));
            float sum = 0.f;
            #pragma unroll
            for (int j = jt; j < 256; j += 32) {
                float e = __expf(S.sc[hloc][j] - m);
                S.sc[hloc][j] = e;
                sum += e;
            }
            #pragma unroll
            for (int o = 16; o; o >>= 1) sum += __shfl_xor_sync(0xffffffffu, sum, o);
            if (jt == 0) g_pml[slot*16 + hloc] = make_float2(m, sum);
        }
    }

    // ======== phase C: O = P * K via tf32 MMA (3-term split) ========
    // warp w owns d-cols [w*16, w*16+16) of each 128-d chunk (2 n-tiles of 8)
    float acc[4][2][4];
    #pragma unroll
    for (int cc = 0; cc < 4; cc++)
        #pragma unroll
        for (int nt = 0; nt < 2; nt++)
            #pragma unroll
            for (int r = 0; r < 4; r++) acc[cc][nt][r] = 0.f;

    #pragma unroll 1
    for (int s = 0; s < 16; s++) {
        CP_WAIT0();
        __syncthreads();
        if (s < 15) {
            int ns = s + 1;
            prefetch_tile(S, buf^1, ns & 3, ns >> 2, selbase, kv, btbl, bq, t);
        }
        int ch = s >> 2, tile = s & 3;
        int kbase = tile << 6;
        const float* pa0 = &S.sc[g4][kbase + l4];
        const float* pa1 = &S.sc[g4+8][kbase + l4];
        const float* kbB = &S.k[buf][0][0];
        int r0base = l4;        // B row (key) = ks*8 + l4
        #pragma unroll
        for (int ks = 0; ks < 8; ks++) {
            int kc_ = ks << 3;
            float a0 = pa0[kc_];
            float a1 = pa1[kc_];
            float a2 = pa0[kc_ + 4];
            float a3 = pa1[kc_ + 4];
            unsigned ah0, ah1, ah2, ah3, al0, al1, al2, al3;
            SPLIT_HL(a0, ah0, al0); SPLIT_HL(a1, ah1, al1);
            SPLIT_HL(a2, ah2, al2); SPLIT_HL(a3, ah3, al3);
            int row0 = kc_ + r0base;       // key row for b0
            int row1 = row0 + 4;           // key row for b1
            const float* kr0 = kbB + (row0 << 7);
            const float* kr1 = kbB + (row1 << 7);
            int sw0 = row0 & 7, sw1 = row1 & 7;
            #pragma unroll
            for (int nt = 0; nt < 2; nt++) {
                int d = (w << 4) + (nt << 3) + g4;   // local d in chunk
                int dg = d >> 2, d3 = d & 3;
                float b0 = kr0[((dg ^ sw0) << 2) + d3];
                float b1 = kr1[((dg ^ sw1) << 2) + d3];
                unsigned bh0, bh1, bl0, bl1;
                SPLIT_HL(b0, bh0, bl0); SPLIT_HL(b1, bh1, bl1);
                float* C = acc[ch][nt];
                mma_tf32(C[0],C[1],C[2],C[3], ah0,ah1,ah2,ah3, bl0,bl1);
                mma_tf32(C[0],C[1],C[2],C[3], al0,al1,al2,al3, bh0,bh1);
                mma_tf32(C[0],C[1],C[2],C[3], ah0,ah1,ah2,ah3, bh0,bh1);
            }
        }
        buf ^= 1;
    }

    // write unnormalized partials
    {
        float* po = g_pO + ((size_t)slot*16)*ND_;
        #pragma unroll
        for (int cc = 0; cc < 4; cc++) {
            #pragma unroll
            for (int nt = 0; nt < 2; nt++) {
                int d = (cc << 7) + (w << 4) + (nt << 3) + (l4 << 1);
                float* C = acc[cc][nt];
                *(float2*)(po + (size_t)g4*ND_ + d)     = make_float2(C[0], C[1]);
                *(float2*)(po + (size_t)(g4+8)*ND_ + d) = make_float2(C[2], C[3]);
            }
        }
    }
}

// ---------------- kernel 5: flash combine + optional key-0 term ----------------
__global__ void combine_kernel(const float* __restrict__ kv,
                               const float* __restrict__ attn_sink,
                               const int* __restrict__ btbl,
                               float* __restrict__ out) {
    __shared__ float k0s[512];
    __shared__ float s0sh[16];
    int hg = blockIdx.x, b = blockIdx.y;
    int t = threadIdx.x;
    int hbase = hg * 16;

    const float* k0 = kv + (size_t)btbl[b << 6] * (BS_ * ND_);
    {
        int i = t * 2;
        *(float2*)(k0s + i) = *(const float2*)(k0 + i);
    }
    __syncthreads();

    int h = t >> 4, ln = t & 15;
    {
        const float* qr = g_qr + ((size_t)b*NH_ + hbase + h)*ND_ + ln*32;
        const float* kk = k0s + ln*32;
        float acc = 0.f;
        #pragma unroll
        for (int i = 0; i < 32; i++) acc = fmaf(qr[i], kk[i], acc);
        #pragma unroll
        for (int o = 8; o; o >>= 1) acc += __shfl_xor_sync(0xffffffffu, acc, o);
        if (ln == 0) s0sh[h] = acc * SCALE_ + attn_sink[hbase + h];
    }
    __syncthreads();

    int dbase = ln * 32;
    int slot0 = (b*4 + hg)*2;
    float2 ml0 = g_pml[slot0*16 + h];
    float2 ml1 = g_pml[(slot0+1)*16 + h];
    int has0 = g_has0[b];
    float sc0 = s0sh[h];
    float M = fmaxf(ml0.x, ml1.x);
    if (!has0) M = fmaxf(M, sc0);
    float a0 = expf(ml0.x - M), a1 = expf(ml1.x - M);
    float a2 = has0 ? 0.f : expf(sc0 - M);
    float inv = 1.f / (ml0.y * a0 + ml1.y * a1 + a2);
    float c0 = a0 * inv, c1 = a1 * inv, c2 = a2 * inv;

    const float* p0 = g_pO + ((size_t)slot0*16 + h)*ND_ + dbase;
    const float* p1 = g_pO + ((size_t)(slot0+1)*16 + h)*ND_ + dbase;
    float* po = out + ((size_t)b*NH_ + hbase + h)*ND_ + dbase;
    #pragma unroll
    for (int i = 0; i < 8; i++) {
        float4 v0 = *(const float4*)(p0 + i*4);
        float4 v1 = *(const float4*)(p1 + i*4);
        float4 vk = *(const float4*)(k0s + dbase + i*4);
        float4 o;
        o.x = v0.x*c0 + v1.x*c1 + vk.x*c2;
        o.y = v0.y*c0 + v1.y*c1 + vk.y*c2;
        o.z = v0.z*c0 + v1.z*c1 + vk.z*c2;
        o.w = v0.w*c0 + v1.w*c1 + vk.w*c2;
        *(float4*)(po + i*4) = o;
    }
}

// ---------------- launch ----------------
extern "C" void kernel_launch(void* const* d_in, const int* in_sizes, int n_in,
                              void* d_out, int out_size) {
    const float* q      = (const float*)d_in[0];
    const float* cosp   = (const float*)d_in[1];
    const float* sinp   = (const float*)d_in[2];
    const float* kv     = (const float*)d_in[3];
    const float* q_idx  = (const float*)d_in[4];
    const float* k_idx  = (const float*)d_in[5];
    const float* sink   = (const float*)d_in[6];
    const int*   btbl   = (const int*)d_in[7];
    const int*   slens  = (const int*)d_in[8];
    float* out = (float*)d_out;

    prep_kernel<<<1280, 256>>>(q, cosp, sinp, q_idx);
    indexer_kernel<<<dim3(16, NB_), 256>>>(k_idx, btbl, slens);
    topk_kernel<<<NB_, 512>>>();

    int smem = (int)sizeof(AttnSmem);
    cudaFuncSetAttribute(attn_kernel, cudaFuncAttributeMaxDynamicSharedMemorySize, smem);
    attn_kernel<<<dim3(4, NB_, 2), 256, smem>>>(kv, sink, btbl);
    combine_kernel<<<dim3(4, NB_), 256>>>(kv, sink, btbl, out);
}

// round 13
// speedup vs baseline: 1.3365x; 1.1358x over previous
#include <cuda_runtime.h>
#include <cuda_bf16.h>
#include <math.h>
#include <stdint.h>

#define NB_  32
#define NH_  64
#define ND_  512
#define NROPE_ 64
#define NHALF_ 32
#define SMAX_ 4096
#define BS_  64
#define IH_  64
#define ID_  128
#define TOPK_ 512
#define SCALE_ 0.04419417382415922f

typedef unsigned long long ull;

// ---------------- scratch ----------------
__device__ float    g_qr[NB_*NH_*ND_];
__device__ unsigned g_qq[NB_*IH_*32];
__device__ float    g_qs[NB_*IH_];
__device__ float    g_w[NB_*ID_];
__device__ float    g_iscore[NB_*SMAX_];
__device__ int      g_sel[NB_*TOPK_];
__device__ int      g_has0[NB_];
__device__ float    g_pO[NB_*4*2*16*512];
__device__ float2   g_pml[NB_*4*2*16];

// ---------------- helpers ----------------
__device__ __forceinline__ void mma_tf32(float& c0, float& c1, float& c2, float& c3,
                                         unsigned a0, unsigned a1, unsigned a2, unsigned a3,
                                         unsigned b0, unsigned b1) {
    asm volatile("mma.sync.aligned.m16n8k8.row.col.f32.tf32.tf32.f32 "
        "{%0,%1,%2,%3}, {%4,%5,%6,%7}, {%8,%9}, {%0,%1,%2,%3};"
        : "+f"(c0), "+f"(c1), "+f"(c2), "+f"(c3)
        : "r"(a0), "r"(a1), "r"(a2), "r"(a3), "r"(b0), "r"(b1));
}

__device__ __forceinline__ void cpa16(void* dst_s, const void* src) {
    unsigned ds = (unsigned)__cvta_generic_to_shared(dst_s);
    asm volatile("cp.async.cg.shared.global [%0], [%1], 16;" :: "r"(ds), "l"(src));
}
#define CP_COMMIT() asm volatile("cp.async.commit_group;")
#define CP_WAIT0()  asm volatile("cp.async.wait_group 0;")

#define SPLIT_HL(x, hi, lo) do { \
    hi = __float_as_uint(x) & 0xFFFFE000u; \
    lo = __float_as_uint((x) - __uint_as_float(hi)); \
} while(0)

// ---------------- kernel 1: fused rope + q_idx quant ----------------
__device__ __forceinline__ int quant1(float x, float scale) {
    float r = rintf(x / scale);
    r = fminf(fmaxf(r, -128.f), 127.f);
    return (int)r;
}

__device__ __forceinline__ float quantf(float x, float scale) {
    float r = rintf(x / scale);
    return fminf(fmaxf(r, -128.f), 127.f);
}

__global__ void prep_kernel(const float* __restrict__ q,
                            const float* __restrict__ cosp,
                            const float* __restrict__ sinp,
                            const float* __restrict__ q_idx) {
    int t = threadIdx.x;
    if (blockIdx.x < 1024) {
        int bh = blockIdx.x * 2 + (t >> 7);
        int b  = bh >> 6;
        int d  = (t & 127) * 4;
        const float* src = q + (size_t)bh * ND_;
        float4 v = *(const float4*)(src + d);
        float4 o;
        if (d < ND_ - NROPE_) {
            o = v;
        } else {
            int i0 = (d - (ND_ - NROPE_)) >> 1;
            float c0 = cosp[b*NHALF_ + i0],   s0 = sinp[b*NHALF_ + i0];
            float c1 = cosp[b*NHALF_ + i0+1], s1 = sinp[b*NHALF_ + i0+1];
            o.x = v.x*c0 - v.y*s0;
            o.y = v.x*s0 + v.y*c0;
            o.z = v.z*c1 - v.w*s1;
            o.w = v.z*s1 + v.w*c1;
        }
        *(float4*)(g_qr + (size_t)bh*ND_ + d) = o;
    } else {
        int row  = (blockIdx.x - 1024) * 8 + (t >> 5);
        int lane = t & 31;
        float4 v = *(const float4*)(q_idx + (size_t)row*ID_ + lane*4);
        float m = fmaxf(fmaxf(fabsf(v.x), fabsf(v.y)), fmaxf(fabsf(v.z), fabsf(v.w)));
        #pragma unroll
        for (int o = 16; o; o >>= 1) m = fmaxf(m, __shfl_xor_sync(0xffffffffu, m, o));
        float scale = fmaxf(m, 1e-12f) * (1.f/127.f);
        if (scale < 1e-6f) scale = 1.f;
        int q0 = quant1(v.x, scale), q1 = quant1(v.y, scale);
        int q2 = quant1(v.z, scale), q3 = quant1(v.w, scale);
        unsigned w = (q0 & 0xFF) | ((q1 & 0xFF) << 8) | ((q2 & 0xFF) << 16) | ((q3 & 0xFF) << 24);
        g_qq[row*32 + lane] = w;
        if (lane == 0) g_qs[row] = scale;
    }
}

// ---------------- kernel 1b: w[b][d] = sum_h qs_h * qq_h[d] ----------------
__global__ void wsum_kernel() {
    int b = blockIdx.x;
    int d = threadIdx.x;              // 128
    int wi  = d >> 2;
    int wsh = (d & 3) << 3;
    float acc = 0.f;
    #pragma unroll 8
    for (int h = 0; h < IH_; h++) {
        unsigned wv = g_qq[(b*IH_ + h)*32 + wi];
        int c = (int)((signed char)((wv >> wsh) & 0xFFu));
        acc = fmaf((float)c, g_qs[b*IH_ + h], acc);
    }
    g_w[b*ID_ + d] = acc;
}

// ---------------- kernel 2: indexer collapsed to one 128-dot per key ----------------
__global__ void __launch_bounds__(256)
indexer_kernel(const float* __restrict__ k_idx_cache,
               const int* __restrict__ btbl,
               const int* __restrict__ seq_lens) {
    __shared__ float sw[ID_];
    int b = blockIdx.y, chunk = blockIdx.x;
    int t = threadIdx.x;
    if (t < ID_) sw[t] = g_w[b*ID_ + t];
    __syncthreads();

    int seqlen = seq_lens[b];
    int s = chunk*256 + t;
    int cs = min(s, seqlen-1);
    int pg = btbl[(b << 6) + (cs >> 6)];
    const float4* kr = (const float4*)(k_idx_cache + ((size_t)pg*BS_ + (cs & 63)) * ID_);

    // pass 1: row abs-max
    float mx = 0.f;
    #pragma unroll
    for (int i = 0; i < 32; i++) {
        float4 v = kr[i];
        mx = fmaxf(mx, fmaxf(fmaxf(fabsf(v.x), fabsf(v.y)), fmaxf(fabsf(v.z), fabsf(v.w))));
    }
    float scale = fmaxf(mx, 1e-12f) * (1.f/127.f);
    if (scale < 1e-6f) scale = 1.f;

    // pass 2 (L1-hot): quantize and dot with w
    float tot = 0.f;
    #pragma unroll
    for (int i = 0; i < 32; i++) {
        float4 v = kr[i];
        float q0 = quantf(v.x, scale);
        float q1 = quantf(v.y, scale);
        float q2 = quantf(v.z, scale);
        float q3 = quantf(v.w, scale);
        tot = fmaf(q0, sw[i*4+0], tot);
        tot = fmaf(q1, sw[i*4+1], tot);
        tot = fmaf(q2, sw[i*4+2], tot);
        tot = fmaf(q3, sw[i*4+3], tot);
    }
    g_iscore[b*SMAX_ + s] = (s < seqlen) ? tot * scale : __int_as_float(0xff800000);
}

// ---------------- kernel 3: exact top-k ----------------
__device__ __forceinline__ int exscan512(int v, int* sh, int* total) {
    int t = threadIdx.x, lane = t & 31, wid = t >> 5;
    __syncthreads();
    int incl = v;
    #pragma unroll
    for (int o = 1; o < 32; o <<= 1) {
        int n = __shfl_up_sync(0xffffffffu, incl, o);
        if (lane >= o) incl += n;
    }
    if (lane == 31) sh[wid] = incl;
    __syncthreads();
    if (wid == 0) {
        int x = (lane < 16) ? sh[lane] : 0;
        #pragma unroll
        for (int o = 1; o < 16; o <<= 1) {
            int n = __shfl_up_sync(0xffffffffu, x, o);
            if (lane >= o) x += n;
        }
        if (lane < 16) sh[lane] = x;
    }
    __syncthreads();
    int base = wid ? sh[wid-1] : 0;
    *total = sh[15];
    return base + incl - v;
}

__device__ __forceinline__ void select_bin(int* hist, int* sscan, int* sinfo, int Krem) {
    int t = threadIdx.x, lane = t & 31, wid = t >> 5;
    int c = (t < 256) ? hist[t] : 0;
    int incl = c;
    #pragma unroll
    for (int o = 1; o < 32; o <<= 1) {
        int n = __shfl_up_sync(0xffffffffu, incl, o);
        if (lane >= o) incl += n;
    }
    if (lane == 31 && wid < 8) sscan[wid] = incl;
    __syncthreads();
    if (wid == 0) {
        int x = (lane < 8) ? sscan[lane] : 0;
        #pragma unroll
        for (int o = 1; o < 8; o <<= 1) {
            int n = __shfl_up_sync(0xffffffffu, x, o);
            if (lane >= o) x += n;
        }
        if (lane < 8) sscan[lane] = x;
        if (lane == 7) sinfo[2] = x;
    }
    __syncthreads();
    if (t < 256) {
        int P = incl + (wid ? sscan[wid-1] : 0);
        int above = sinfo[2] - P;
        if (above < Krem && Krem <= above + c) {
            sinfo[0] = t;
            sinfo[1] = Krem - above;
        }
    }
    __syncthreads();
}

__global__ void topk_kernel() {
    int b = blockIdx.x;
    __shared__ unsigned skey[SMAX_];
    __shared__ unsigned cand[SMAX_];
    __shared__ int hist[256];
    __shared__ int sscan[17];
    __shared__ int sinfo[3];
    __shared__ int ccnt;
    int t = threadIdx.x;

    for (int i = t; i < SMAX_; i += 512) {
        unsigned u = __float_as_uint(g_iscore[b*SMAX_ + i]);
        skey[i] = (u & 0x80000000u) ? ~u : (u | 0x80000000u);
    }
    if (t == 0) ccnt = 0;
    if (t < 256) hist[t] = 0;
    __syncthreads();

    for (int i = t; i < SMAX_; i += 512)
        atomicAdd((unsigned*)&hist[skey[i] >> 24], 1u);
    __syncthreads();
    select_bin(hist, sscan, sinfo, TOPK_);
    unsigned b1 = (unsigned)sinfo[0];
    unsigned prefix = b1 << 24;
    int Krem = sinfo[1];

    for (int i = t; i < SMAX_; i += 512) {
        unsigned u = skey[i];
        if ((u >> 24) == b1) cand[atomicAdd((unsigned*)&ccnt, 1u)] = u;
    }
    __syncthreads();
    int L = ccnt;
    unsigned mask = 0xFF000000u;

    for (int shift = 16; shift >= 0; shift -= 8) {
        if (t < 256) hist[t] = 0;
        __syncthreads();
        for (int i = t; i < L; i += 512) {
            unsigned u = cand[i];
            if ((u & mask) == prefix) atomicAdd((unsigned*)&hist[(u >> shift) & 255], 1u);
        }
        __syncthreads();
        select_bin(hist, sscan, sinfo, Krem);
        prefix |= ((unsigned)sinfo[0]) << shift;
        mask   |= 0xFFu << shift;
        Krem = sinfo[1];
    }
    unsigned T = prefix;
    int R = Krem;

    int base = t * 8;
    int eqc = 0;
    #pragma unroll
    for (int i = 0; i < 8; i++) eqc += (skey[base+i] == T);
    int tot;
    int eqoff = exscan512(eqc, sscan, &tot);

    int kc = 0;
    unsigned kmask = 0;
    int er = eqoff;
    #pragma unroll
    for (int i = 0; i < 8; i++) {
        unsigned u = skey[base+i];
        bool eq = (u == T);
        bool kp = (u > T) || (eq && er < R);
        er += eq;
        if (base + i == 0) g_has0[b] = kp ? 1 : 0;
        kmask |= (unsigned)kp << i;
        kc += kp;
    }
    int koff = exscan512(kc, sscan, &tot);
    int p = koff;
    #pragma unroll
    for (int i = 0; i < 8; i++) {
        if ((kmask >> i) & 1) g_sel[b*TOPK_ + p++] = base + i;
    }
}

// ---------------- kernel 4: split-KV attention; A and C on tf32 MMA ----------------
#define QSTR 516
#define SCSTR 260

struct AttnSmem {
    float q[16*QSTR];        // 33024
    float k[2][64][128];     // 65536 swizzled
    float sc[16][SCSTR];     // 16640
};                           // 115200 B

extern __shared__ char smem_raw[];

__device__ __forceinline__ void prefetch_tile(AttnSmem& S, int buf, int tile, int ch,
                                              int selbase,
                                              const float* __restrict__ kv,
                                              const int* __restrict__ btbl,
                                              int bq, int t) {
    int kbase = tile << 6;
    int g = t & 31;
    int dstg = g ^ ((t >> 5) & 7);
    #pragma unroll
    for (int i = 0; i < 8; i++) {
        int r = (t >> 5) + (i << 3);
        int sp = g_sel[selbase + kbase + r];
        int pg = btbl[bq + (sp >> 6)];
        const float* src = kv + ((size_t)pg*BS_ + (sp & 63)) * ND_ + (ch << 7) + (g << 2);
        cpa16(&S.k[buf][r][dstg << 2], src);
    }
    CP_COMMIT();
}

__global__ void __launch_bounds__(256, 2)
attn_kernel(const float* __restrict__ kv,
            const float* __restrict__ attn_sink,
            const int* __restrict__ btbl) {
    AttnSmem& S = *(AttnSmem*)smem_raw;
    int hg = blockIdx.x, b = blockIdx.y, split = blockIdx.z;
    int t = threadIdx.x;
    int hbase = hg * 16;
    int selbase = b*TOPK_ + split*256;
    int bq = b << 6;
    int slot = (b*4 + hg)*2 + split;

    {
        const float* qr = g_qr + ((size_t)b*NH_ + hbase) * ND_;
        for (int i = t*4; i < 16*ND_; i += 1024) {
            int row = i >> 9, col = i & 511;
            *(float4*)&S.q[row*QSTR + col] = *(const float4*)(qr + i);
        }
    }
    prefetch_tile(S, 0, 0, 0, selbase, kv, btbl, bq, t);
    __syncthreads();

    int w    = t >> 5;
    int lane = t & 31;
    int g4 = lane >> 2, l4 = lane & 3;

    // ======== phase A: scores via tf32 MMA (3-term split) ========
    float c0 = 0.f, c1 = 0.f, c2 = 0.f, c3 = 0.f;
    int buf = 0;
    int rloc = (w << 3) + g4;
    #pragma unroll 1
    for (int s = 0; s < 16; s++) {
        CP_WAIT0();
        __syncthreads();
        if (s < 15) prefetch_tile(S, buf^1, (s+1) >> 2, (s+1) & 3, selbase, kv, btbl, bq, t);
        else        prefetch_tile(S, buf^1, 0, 0, selbase, kv, btbl, bq, t);
        int tile = s >> 2, ch = s & 3;
        if (ch == 0) { c0 = 0.f; c1 = 0.f; c2 = 0.f; c3 = 0.f; }
        const float* kb  = &S.k[buf][rloc][0];
        const float* q0p = &S.q[g4*QSTR + (ch << 7) + l4];
        const float* q1p = &S.q[(g4+8)*QSTR + (ch << 7) + l4];
        #pragma unroll
        for (int ks = 0; ks < 16; ks++) {
            int k0 = ks << 3;
            float a0 = q0p[k0];
            float a1 = q1p[k0];
            float a2 = q0p[k0 + 4];
            float a3 = q1p[k0 + 4];
            int gb = k0 >> 2;
            float b0 = kb[((gb ^ g4) << 2) + l4];
            float b1 = kb[(((gb + 1) ^ g4) << 2) + l4];
            unsigned ah0, ah1, ah2, ah3, al0, al1, al2, al3, bh0, bh1, bl0, bl1;
            SPLIT_HL(a0, ah0, al0); SPLIT_HL(a1, ah1, al1);
            SPLIT_HL(a2, ah2, al2); SPLIT_HL(a3, ah3, al3);
            SPLIT_HL(b0, bh0, bl0); SPLIT_HL(b1, bh1, bl1);
            mma_tf32(c0,c1,c2,c3, ah0,ah1,ah2,ah3, bl0,bl1);
            mma_tf32(c0,c1,c2,c3, al0,al1,al2,al3, bh0,bh1);
            mma_tf32(c0,c1,c2,c3, ah0,ah1,ah2,ah3, bh0,bh1);
        }
        if (ch == 3) {
            int j0 = (tile << 6) + (w << 3) + (l4 << 1);
            S.sc[g4][j0]     = c0 * SCALE_;
            S.sc[g4][j0+1]   = c1 * SCALE_;
            S.sc[g4+8][j0]   = c2 * SCALE_;
            S.sc[g4+8][j0+1] = c3 * SCALE_;
        }
        buf ^= 1;
    }
    __syncthreads();

    if (split == 0 && t < 16) {
        if (g_sel[selbase] == 0) S.sc[t][0] += attn_sink[hbase + t];
    }
    __syncthreads();

    // ======== softmax partials (warp per 2 heads) ========
    {
        int jt = t & 31;
        #pragma unroll
        for (int hh = 0; hh < 2; hh++) {
            int hloc = 2*w + hh;
            float m = -3.4e38f;
            #pragma unroll
            for (int j = jt; j < 256; j += 32) m = fmaxf(m, S.sc[hloc][j]);
            #pragma unroll
            for (int o = 16; o; o >>= 1) m = fmaxf(m, __shfl_xor_sync(0xffffffffu, m, o));
            float sum = 0.f;
            #pragma unroll
            for (int j = jt; j < 256; j += 32) {
                float e = __expf(S.sc[hloc][j] - m);
                S.sc[hloc][j] = e;
                sum += e;
            }
            #pragma unroll
            for (int o = 16; o; o >>= 1) sum += __shfl_xor_sync(0xffffffffu, sum, o);
            if (jt == 0) g_pml[slot*16 + hloc] = make_float2(m, sum);
        }
    }

    // ======== phase C: O = P * K via tf32 MMA (3-term split) ========
    float acc[4][2][4];
    #pragma unroll
    for (int cc = 0; cc < 4; cc++)
        #pragma unroll
        for (int nt = 0; nt < 2; nt++)
            #pragma unroll
            for (int r = 0; r < 4; r++) acc[cc][nt][r] = 0.f;

    #pragma unroll 1
    for (int s = 0; s < 16; s++) {
        CP_WAIT0();
        __syncthreads();
        if (s < 15) {
            int ns = s + 1;
            prefetch_tile(S, buf^1, ns & 3, ns >> 2, selbase, kv, btbl, bq, t);
        }
        int ch = s >> 2, tile = s & 3;
        int kbase = tile << 6;
        const float* pa0 = &S.sc[g4][kbase + l4];
        const float* pa1 = &S.sc[g4+8][kbase + l4];
        const float* kbB = &S.k[buf][0][0];
        int r0base = l4;
        #pragma unroll
        for (int ks = 0; ks < 8; ks++) {
            int kc_ = ks << 3;
            float a0 = pa0[kc_];
            float a1 = pa1[kc_];
            float a2 = pa0[kc_ + 4];
            float a3 = pa1[kc_ + 4];
            unsigned ah0, ah1, ah2, ah3, al0, al1, al2, al3;
            SPLIT_HL(a0, ah0, al0); SPLIT_HL(a1, ah1, al1);
            SPLIT_HL(a2, ah2, al2); SPLIT_HL(a3, ah3, al3);
            int row0 = kc_ + r0base;
            int row1 = row0 + 4;
            const float* kr0 = kbB + (row0 << 7);
            const float* kr1 = kbB + (row1 << 7);
            int sw0 = row0 & 7, sw1 = row1 & 7;
            #pragma unroll
            for (int nt = 0; nt < 2; nt++) {
                int d = (w << 4) + (nt << 3) + g4;
                int dg = d >> 2, d3 = d & 3;
                float b0 = kr0[((dg ^ sw0) << 2) + d3];
                float b1 = kr1[((dg ^ sw1) << 2) + d3];
                unsigned bh0, bh1, bl0, bl1;
                SPLIT_HL(b0, bh0, bl0); SPLIT_HL(b1, bh1, bl1);
                float* C = acc[ch][nt];
                mma_tf32(C[0],C[1],C[2],C[3], ah0,ah1,ah2,ah3, bl0,bl1);
                mma_tf32(C[0],C[1],C[2],C[3], al0,al1,al2,al3, bh0,bh1);
                mma_tf32(C[0],C[1],C[2],C[3], ah0,ah1,ah2,ah3, bh0,bh1);
            }
        }
        buf ^= 1;
    }

    {
        float* po = g_pO + ((size_t)slot*16)*ND_;
        #pragma unroll
        for (int cc = 0; cc < 4; cc++) {
            #pragma unroll
            for (int nt = 0; nt < 2; nt++) {
                int d = (cc << 7) + (w << 4) + (nt << 3) + (l4 << 1);
                float* C = acc[cc][nt];
                *(float2*)(po + (size_t)g4*ND_ + d)     = make_float2(C[0], C[1]);
                *(float2*)(po + (size_t)(g4+8)*ND_ + d) = make_float2(C[2], C[3]);
            }
        }
    }
}

// ---------------- kernel 5: flash combine + optional key-0 term ----------------
__global__ void combine_kernel(const float* __restrict__ kv,
                               const float* __restrict__ attn_sink,
                               const int* __restrict__ btbl,
                               float* __restrict__ out) {
    __shared__ float k0s[512];
    __shared__ float s0sh[16];
    int hg = blockIdx.x, b = blockIdx.y;
    int t = threadIdx.x;
    int hbase = hg * 16;

    const float* k0 = kv + (size_t)btbl[b << 6] * (BS_ * ND_);
    {
        int i = t * 2;
        *(float2*)(k0s + i) = *(const float2*)(k0 + i);
    }
    __syncthreads();

    int h = t >> 4, ln = t & 15;
    {
        const float* qr = g_qr + ((size_t)b*NH_ + hbase + h)*ND_ + ln*32;
        const float* kk = k0s + ln*32;
        float acc = 0.f;
        #pragma unroll
        for (int i = 0; i < 32; i++) acc = fmaf(qr[i], kk[i], acc);
        #pragma unroll
        for (int o = 8; o; o >>= 1) acc += __shfl_xor_sync(0xffffffffu, acc, o);
        if (ln == 0) s0sh[h] = acc * SCALE_ + attn_sink[hbase + h];
    }
    __syncthreads();

    int dbase = ln * 32;
    int slot0 = (b*4 + hg)*2;
    float2 ml0 = g_pml[slot0*16 + h];
    float2 ml1 = g_pml[(slot0+1)*16 + h];
    int has0 = g_has0[b];
    float sc0 = s0sh[h];
    float M = fmaxf(ml0.x, ml1.x);
    if (!has0) M = fmaxf(M, sc0);
    float a0 = expf(ml0.x - M), a1 = expf(ml1.x - M);
    float a2 = has0 ? 0.f : expf(sc0 - M);
    float inv = 1.f / (ml0.y * a0 + ml1.y * a1 + a2);
    float c0 = a0 * inv, c1 = a1 * inv, c2 = a2 * inv;

    const float* p0 = g_pO + ((size_t)slot0*16 + h)*ND_ + dbase;
    const float* p1 = g_pO + ((size_t)(slot0+1)*16 + h)*ND_ + dbase;
    float* po = out + ((size_t)b*NH_ + hbase + h)*ND_ + dbase;
    #pragma unroll
    for (int i = 0; i < 8; i++) {
        float4 v0 = *(const float4*)(p0 + i*4);
        float4 v1 = *(const float4*)(p1 + i*4);
        float4 vk = *(const float4*)(k0s + dbase + i*4);
        float4 o;
        o.x = v0.x*c0 + v1.x*c1 + vk.x*c2;
        o.y = v0.y*c0 + v1.y*c1 + vk.y*c2;
        o.z = v0.z*c0 + v1.z*c1 + vk.z*c2;
        o.w = v0.w*c0 + v1.w*c1 + vk.w*c2;
        *(float4*)(po + i*4) = o;
    }
}

// ---------------- launch ----------------
extern "C" void kernel_launch(void* const* d_in, const int* in_sizes, int n_in,
                              void* d_out, int out_size) {
    const float* q      = (const float*)d_in[0];
    const float* cosp   = (const float*)d_in[1];
    const float* sinp   = (const float*)d_in[2];
    const float* kv     = (const float*)d_in[3];
    const float* q_idx  = (const float*)d_in[4];
    const float* k_idx  = (const float*)d_in[5];
    const float* sink   = (const float*)d_in[6];
    const int*   btbl   = (const int*)d_in[7];
    const int*   slens  = (const int*)d_in[8];
    float* out = (float*)d_out;

    prep_kernel<<<1280, 256>>>(q, cosp, sinp, q_idx);
    wsum_kernel<<<NB_, ID_>>>();
    indexer_kernel<<<dim3(16, NB_), 256>>>(k_idx, btbl, slens);
    topk_kernel<<<NB_, 512>>>();

    int smem = (int)sizeof(AttnSmem);
    cudaFuncSetAttribute(attn_kernel, cudaFuncAttributeMaxDynamicSharedMemorySize, smem);
    attn_kernel<<<dim3(4, NB_, 2), 256, smem>>>(kv, sink, btbl);
    combine_kernel<<<dim3(4, NB_), 256>>>(kv, sink, btbl, out);
}